// round 13
// baseline (speedup 1.0000x reference)
#include <cuda_runtime.h>
#include <cuda_bf16.h>
#include <cstdint>

// Problem constants
#define B_TOT   2048
#define N_TOK   98
#define C_DIM   256
#define H_NUM   8
#define HD      32
#define NW      512
#define M_ROWS  (B_TOT * N_TOK)          // 200704
#define QKV_N   (3 * C_DIM)              // 768

// -------- scratch (static device globals; device-code refs ONLY) --------
__device__ __nv_bfloat16 g_qkv_hi[(size_t)M_ROWS * QKV_N];
__device__ __nv_bfloat16 g_qkv_lo[(size_t)M_ROWS * QKV_N];
__device__ __nv_bfloat16 g_att_hi[(size_t)M_ROWS * C_DIM];
__device__ __nv_bfloat16 g_att_lo[(size_t)M_ROWS * C_DIM];
__device__ __nv_bfloat16 g_w_hi[QKV_N * C_DIM + C_DIM * C_DIM];
__device__ __nv_bfloat16 g_w_lo[QKV_N * C_DIM + C_DIM * C_DIM];
__device__ float g_bias[H_NUM * N_TOK * N_TOK];

// ================= helpers =================
__device__ __forceinline__ uint32_t smem_u32(const void* p) {
    uint32_t a;
    asm("{ .reg .u64 t; cvta.to.shared.u64 t, %1; cvt.u32.u64 %0, t; }"
        : "=r"(a) : "l"(p));
    return a;
}

__device__ __forceinline__ void mma16816(float* c, const uint32_t* a, const uint32_t* b) {
    asm volatile(
        "mma.sync.aligned.m16n8k16.row.col.f32.bf16.bf16.f32 "
        "{%0,%1,%2,%3}, {%4,%5,%6,%7}, {%8,%9}, {%0,%1,%2,%3};"
        : "+f"(c[0]), "+f"(c[1]), "+f"(c[2]), "+f"(c[3])
        : "r"(a[0]), "r"(a[1]), "r"(a[2]), "r"(a[3]), "r"(b[0]), "r"(b[1]));
}

__device__ __forceinline__ void ldsm4(uint32_t* r, uint32_t addr) {
    asm volatile("ldmatrix.sync.aligned.m8n8.x4.shared.b16 {%0,%1,%2,%3}, [%4];"
                 : "=r"(r[0]), "=r"(r[1]), "=r"(r[2]), "=r"(r[3]) : "r"(addr));
}

__device__ __forceinline__ void split2(float x, float y, uint32_t& hi, uint32_t& lo) {
    __nv_bfloat16 hx = __float2bfloat16(x);
    __nv_bfloat16 hy = __float2bfloat16(y);
    __nv_bfloat16 lx = __float2bfloat16(x - __bfloat162float(hx));
    __nv_bfloat16 ly = __float2bfloat16(y - __bfloat162float(hy));
    hi = (uint32_t)__bfloat16_as_ushort(hx) | ((uint32_t)__bfloat16_as_ushort(hy) << 16);
    lo = (uint32_t)__bfloat16_as_ushort(lx) | ((uint32_t)__bfloat16_as_ushort(ly) << 16);
}

__device__ __forceinline__ uint32_t lds32(const char* p) {
    return *reinterpret_cast<const uint32_t*>(p);
}

// ---------------------------------------------------------------
// Kernel 0: presplit weights (1 MB total) -> bf16 hi/lo
// ---------------------------------------------------------------
__global__ void presplit_w_kernel(const float* __restrict__ qkv_w,
                                  const float* __restrict__ proj_w) {
    const int nq = QKV_N * C_DIM / 4;       // 49152
    const int np = C_DIM * C_DIM / 4;       // 16384
    int i = blockIdx.x * blockDim.x + threadIdx.x;
    for (; i < nq + np; i += gridDim.x * blockDim.x) {
        const float* src = (i < nq) ? qkv_w + 4 * (size_t)i
                                    : proj_w + 4 * (size_t)(i - nq);
        float4 v = *reinterpret_cast<const float4*>(src);
        uint32_t h01, l01, h23, l23;
        split2(v.x, v.y, h01, l01);
        split2(v.z, v.w, h23, l23);
        *reinterpret_cast<uint2*>(g_w_hi + 4 * (size_t)i) = make_uint2(h01, h23);
        *reinterpret_cast<uint2*>(g_w_lo + 4 * (size_t)i) = make_uint2(l01, l23);
    }
}

// ---------------------------------------------------------------
// Kernel 1: gather relative-position bias  -> g_bias[h][n][m]
// ---------------------------------------------------------------
__global__ void gather_bias_kernel(const float* __restrict__ table,
                                   const int* __restrict__ rel) {
    int idx = blockIdx.x * blockDim.x + threadIdx.x;
    const int total = H_NUM * N_TOK * N_TOK;
    if (idx < total) {
        int h  = idx / (N_TOK * N_TOK);
        int nm = idx % (N_TOK * N_TOK);
        g_bias[idx] = table[rel[nm] * H_NUM + h];
    }
}

// ---------------------------------------------------------------
// HMMA bf16x3 split GEMM (R11 skeleton: LDG prefetch + STS, double
// buffer, scalar-LDS fragments, term-major mma). W always presplit.
// ---------------------------------------------------------------
#define RB    80          // row bytes (40 halves)
#define REG_B 10240       // region bytes
#define BUF_B 40960       // buffer bytes

// scalar-LDS fragments, term-major (proven R11)
__device__ __forceinline__ void compute_chunk_s(const char* sbuf, int wm, int wn,
                                                int lane, float acc[2][8][4]) {
    const int g = lane >> 2;
    const int t = lane & 3;
#pragma unroll
    for (int ks = 0; ks < 32; ks += 16) {
        uint32_t ah[2][4], al[2][4];
#pragma unroll
        for (int mt = 0; mt < 2; mt++) {
            const char* a0p = sbuf + (wm + mt * 16 + g) * RB + (ks + 2 * t) * 2;
            ah[mt][0] = lds32(a0p);
            ah[mt][1] = lds32(a0p + 8 * RB);
            ah[mt][2] = lds32(a0p + 16);
            ah[mt][3] = lds32(a0p + 8 * RB + 16);
            al[mt][0] = lds32(a0p + REG_B);
            al[mt][1] = lds32(a0p + REG_B + 8 * RB);
            al[mt][2] = lds32(a0p + REG_B + 16);
            al[mt][3] = lds32(a0p + REG_B + 8 * RB + 16);
        }
#pragma unroll
        for (int qh = 0; qh < 2; qh++) {
            uint32_t bh[4][2], bl[4][2];
#pragma unroll
            for (int q4 = 0; q4 < 4; q4++) {
                const char* b0p = sbuf + 2 * REG_B
                    + (wn + (qh * 4 + q4) * 8 + g) * RB + (ks + 2 * t) * 2;
                bh[q4][0] = lds32(b0p);
                bh[q4][1] = lds32(b0p + 16);
                bl[q4][0] = lds32(b0p + REG_B);
                bl[q4][1] = lds32(b0p + REG_B + 16);
            }
#pragma unroll
            for (int q4 = 0; q4 < 4; q4++)
#pragma unroll
                for (int mt = 0; mt < 2; mt++)
                    mma16816(acc[mt][qh * 4 + q4], ah[mt], bh[q4]);
#pragma unroll
            for (int q4 = 0; q4 < 4; q4++)
#pragma unroll
                for (int mt = 0; mt < 2; mt++)
                    mma16816(acc[mt][qh * 4 + q4], ah[mt], bl[q4]);
#pragma unroll
            for (int q4 = 0; q4 < 4; q4++)
#pragma unroll
                for (int mt = 0; mt < 2; mt++)
                    mma16816(acc[mt][qh * 4 + q4], al[mt], bh[q4]);
        }
    }
}

// ---------- QKV GEMM: A = x (fp32, split in-loop); W presplit ----------
__global__ void __launch_bounds__(256, 2)
qkv_gemm_kernel(const float* __restrict__ x, const float* __restrict__ bias) {
    extern __shared__ char smem[];
    const int tid  = threadIdx.x;
    const int wid  = tid >> 5;
    const int lane = tid & 31;
    const int m0 = blockIdx.y * 128;
    const int n0 = blockIdx.x * 128;
    const int wm = (wid >> 1) * 32;
    const int wn = (wid & 1) * 64;
    const __nv_bfloat16* Wh = g_w_hi;
    const __nv_bfloat16* Wl = g_w_lo;

    // per-thread load slots (R11): f4 = tid + i*256, row = f4>>3, c4 = (f4&7)*4
    float acc[2][8][4];
#pragma unroll
    for (int mt = 0; mt < 2; mt++)
#pragma unroll
        for (int nt = 0; nt < 8; nt++)
#pragma unroll
            for (int j = 0; j < 4; j++) acc[mt][nt][j] = 0.f;

    float4 ra[4];
    uint2  wh[4], wl[4];

    auto ld = [&](int k0) {
#pragma unroll
        for (int i = 0; i < 4; i++) {
            int f4  = tid + i * 256;
            int row = f4 >> 3;
            int c4  = (f4 & 7) << 2;
            ra[i] = *reinterpret_cast<const float4*>(x + (size_t)(m0 + row) * C_DIM + k0 + c4);
            size_t gw = (size_t)(n0 + row) * C_DIM + k0 + c4;
            wh[i] = *reinterpret_cast<const uint2*>(Wh + gw);
            wl[i] = *reinterpret_cast<const uint2*>(Wl + gw);
        }
    };
    auto st = [&](char* buf) {
#pragma unroll
        for (int i = 0; i < 4; i++) {
            int f4  = tid + i * 256;
            int row = f4 >> 3;
            int c4  = (f4 & 7) << 2;
            int off = row * RB + c4 * 2;
            uint32_t h01, l01, h23, l23;
            split2(ra[i].x, ra[i].y, h01, l01);
            split2(ra[i].z, ra[i].w, h23, l23);
            *reinterpret_cast<uint2*>(buf + off)             = make_uint2(h01, h23);
            *reinterpret_cast<uint2*>(buf + REG_B + off)     = make_uint2(l01, l23);
            *reinterpret_cast<uint2*>(buf + 2 * REG_B + off) = wh[i];
            *reinterpret_cast<uint2*>(buf + 3 * REG_B + off) = wl[i];
        }
    };

    ld(0);
    st(smem);
    __syncthreads();

#pragma unroll 1
    for (int ch = 0; ch < 8; ch++) {
        if (ch < 7) ld((ch + 1) * 32);
        compute_chunk_s(smem + (ch & 1) * BUF_B, wm, wn, lane, acc);
        if (ch < 7) st(smem + ((ch + 1) & 1) * BUF_B);
        __syncthreads();
    }

    // epilogue: split bf16 hi/lo output; q (cols < 256) pre-scaled
    const int g = lane >> 2;
    const int t = lane & 3;
    const float f = (n0 < 256) ? 0.17677669529663687f : 1.f;
#pragma unroll
    for (int mt = 0; mt < 2; mt++) {
#pragma unroll
        for (int q = 0; q < 8; q++) {
            int rr = m0 + wm + mt * 16 + g;
            int cc = n0 + wn + q * 8 + 2 * t;
            float b0 = bias[cc], b1 = bias[cc + 1];
            uint32_t hi, lo;
            split2((acc[mt][q][0] + b0) * f, (acc[mt][q][1] + b1) * f, hi, lo);
            *reinterpret_cast<uint32_t*>(g_qkv_hi + (size_t)rr * QKV_N + cc) = hi;
            *reinterpret_cast<uint32_t*>(g_qkv_lo + (size_t)rr * QKV_N + cc) = lo;
            split2((acc[mt][q][2] + b0) * f, (acc[mt][q][3] + b1) * f, hi, lo);
            *reinterpret_cast<uint32_t*>(g_qkv_hi + (size_t)(rr + 8) * QKV_N + cc) = hi;
            *reinterpret_cast<uint32_t*>(g_qkv_lo + (size_t)(rr + 8) * QKV_N + cc) = lo;
        }
    }
}

// ---------- proj GEMM: A = g_att presplit; W presplit; fp32 out ----------
__global__ void __launch_bounds__(256, 2)
proj_gemm_kernel(const float* __restrict__ bias, float* __restrict__ out) {
    extern __shared__ char smem[];
    const int tid  = threadIdx.x;
    const int wid  = tid >> 5;
    const int lane = tid & 31;
    const int m0 = blockIdx.y * 128;
    const int n0 = blockIdx.x * 128;
    const int wm = (wid >> 1) * 32;
    const int wn = (wid & 1) * 64;
    const __nv_bfloat16* Ah = g_att_hi;
    const __nv_bfloat16* Al = g_att_lo;
    const __nv_bfloat16* Wh = g_w_hi + QKV_N * C_DIM;
    const __nv_bfloat16* Wl = g_w_lo + QKV_N * C_DIM;

    float acc[2][8][4];
#pragma unroll
    for (int mt = 0; mt < 2; mt++)
#pragma unroll
        for (int nt = 0; nt < 8; nt++)
#pragma unroll
            for (int j = 0; j < 4; j++) acc[mt][nt][j] = 0.f;

    uint2 ahr[4], alr[4], whr[4], wlr[4];

    auto ld = [&](int k0) {
#pragma unroll
        for (int i = 0; i < 4; i++) {
            int f4  = tid + i * 256;
            int row = f4 >> 3;
            int c4  = (f4 & 7) << 2;
            size_t ga = (size_t)(m0 + row) * C_DIM + k0 + c4;
            size_t gw = (size_t)(n0 + row) * C_DIM + k0 + c4;
            ahr[i] = *reinterpret_cast<const uint2*>(Ah + ga);
            alr[i] = *reinterpret_cast<const uint2*>(Al + ga);
            whr[i] = *reinterpret_cast<const uint2*>(Wh + gw);
            wlr[i] = *reinterpret_cast<const uint2*>(Wl + gw);
        }
    };
    auto st = [&](char* buf) {
#pragma unroll
        for (int i = 0; i < 4; i++) {
            int f4  = tid + i * 256;
            int row = f4 >> 3;
            int c4  = (f4 & 7) << 2;
            int off = row * RB + c4 * 2;
            *reinterpret_cast<uint2*>(buf + off)             = ahr[i];
            *reinterpret_cast<uint2*>(buf + REG_B + off)     = alr[i];
            *reinterpret_cast<uint2*>(buf + 2 * REG_B + off) = whr[i];
            *reinterpret_cast<uint2*>(buf + 3 * REG_B + off) = wlr[i];
        }
    };

    ld(0);
    st(smem);
    __syncthreads();

#pragma unroll 1
    for (int ch = 0; ch < 8; ch++) {
        if (ch < 7) ld((ch + 1) * 32);
        compute_chunk_s(smem + (ch & 1) * BUF_B, wm, wn, lane, acc);
        if (ch < 7) st(smem + ((ch + 1) & 1) * BUF_B);
        __syncthreads();
    }

    const int g = lane >> 2;
    const int t = lane & 3;
#pragma unroll
    for (int mt = 0; mt < 2; mt++) {
#pragma unroll
        for (int q = 0; q < 8; q++) {
            int rr = m0 + wm + mt * 16 + g;
            int cc = n0 + wn + q * 8 + 2 * t;
            float b0 = bias[cc], b1 = bias[cc + 1];
            float2 v0 = make_float2(acc[mt][q][0] + b0, acc[mt][q][1] + b1);
            float2 v1 = make_float2(acc[mt][q][2] + b0, acc[mt][q][3] + b1);
            *reinterpret_cast<float2*>(out + (size_t)rr * C_DIM + cc)       = v0;
            *reinterpret_cast<float2*>(out + (size_t)(rr + 8) * C_DIM + cc) = v1;
        }
    }
}

// ---------------------------------------------------------------
// Kernel 3: HMMA attention (R10/R11 proven: ldmatrix + register
// softmax), presplit inputs (copies only in phase 0), split output.
// One CTA per (b,h). smem 89088 -> 2 CTAs/SM.
// ---------------------------------------------------------------
#define PM    128
#define PRB   272                 // P row pitch (bytes)
#define PREG  (PM * PRB)          // 34816
#define VRB   272
#define VREG  (HD * VRB)          // 8704
#define OFF_VT   (2 * PREG)             // 69632
#define OFF_RED  (OFF_VT + 2 * VREG)    // 87040
#define ATTN_SMEM (OFF_RED + 2048)      // 89088

// ldmatrix chunk for attention QK^T (RB=80 layout), term-major
__device__ __forceinline__ void compute_chunk_l(uint32_t sbuf, int wm, int wn,
                                                int lane, float acc[2][8][4]) {
    const int arow  = lane & 15;
    const int acol2 = ((lane >> 4) << 3) * 2;
    const int brow  = (lane & 7) + ((lane >> 3) & 2) * 4;
    const int bcol2 = (((lane >> 3) & 1) << 3) * 2;
#pragma unroll
    for (int ks = 0; ks < 32; ks += 16) {
        uint32_t ah[2][4], al[2][4];
#pragma unroll
        for (int mt = 0; mt < 2; mt++) {
            uint32_t aaddr = sbuf + (wm + mt * 16 + arow) * RB + ks * 2 + acol2;
            ldsm4(ah[mt], aaddr);
            ldsm4(al[mt], aaddr + REG_B);
        }
#pragma unroll
        for (int qp = 0; qp < 4; qp++) {
            uint32_t baddr = sbuf + 2 * REG_B + (wn + qp * 16 + brow) * RB + ks * 2 + bcol2;
            uint32_t bh[4], bl[4];
            ldsm4(bh, baddr);
            ldsm4(bl, baddr + REG_B);
#pragma unroll
            for (int hf = 0; hf < 2; hf++)
#pragma unroll
                for (int mt = 0; mt < 2; mt++)
                    mma16816(acc[mt][qp * 2 + hf], ah[mt], bh + 2 * hf);
#pragma unroll
            for (int hf = 0; hf < 2; hf++)
#pragma unroll
                for (int mt = 0; mt < 2; mt++)
                    mma16816(acc[mt][qp * 2 + hf], ah[mt], bl + 2 * hf);
#pragma unroll
            for (int hf = 0; hf < 2; hf++)
#pragma unroll
                for (int mt = 0; mt < 2; mt++)
                    mma16816(acc[mt][qp * 2 + hf], al[mt], bh + 2 * hf);
        }
    }
}

__global__ void __launch_bounds__(256, 2)
attn_hmma_kernel(const float* __restrict__ mask) {
    extern __shared__ char smem[];
    const int tid  = threadIdx.x;
    const int wid  = tid >> 5;
    const int lane = tid & 31;
    const int g = lane >> 2;
    const int t = lane & 3;
    const int bh = blockIdx.x;
    const int b  = bh >> 3;
    const int h  = bh & 7;

    char*  qk = smem;                    // q hi/lo, k hi/lo (RB=80), phase 1 only
    char*  Pz = smem;                    // P hi/lo (overlays qk after sync)
    char*  vt = smem + OFF_VT;
    float* redM = reinterpret_cast<float*>(smem + OFF_RED);        // [2][128]
    float* redS = redM + 256;                                      // [2][128]
    const uint32_t sb = smem_u32(smem);

    // ---- phase 0: copy presplit q,k into RB=80 layout; build V^T ----
#pragma unroll
    for (int i = 0; i < 4; i++) {
        int s = tid + 256 * i;          // 1024 slots: 128 rows x 8 quads (4 halves)
        int row = s >> 3;
        int c4  = (s & 7) << 2;
        uint2 qh = make_uint2(0u, 0u), ql = qh, kh = qh, kl = qh;
        if (row < N_TOK) {
            size_t base = ((size_t)(b * N_TOK + row)) * QKV_N + h * HD + c4;
            qh = *reinterpret_cast<const uint2*>(g_qkv_hi + base);
            ql = *reinterpret_cast<const uint2*>(g_qkv_lo + base);
            kh = *reinterpret_cast<const uint2*>(g_qkv_hi + base + C_DIM);
            kl = *reinterpret_cast<const uint2*>(g_qkv_lo + base + C_DIM);
        }
        int off = row * RB + c4 * 2;
        *reinterpret_cast<uint2*>(qk + off)             = qh;
        *reinterpret_cast<uint2*>(qk + REG_B + off)     = ql;
        *reinterpret_cast<uint2*>(qk + 2 * REG_B + off) = kh;
        *reinterpret_cast<uint2*>(qk + 3 * REG_B + off) = kl;
    }
    // V^T: vt[d][token-pair] bf16 hi/lo
#pragma unroll
    for (int i = 0; i < 2; i++) {
        int s  = tid + 256 * i;          // 512 slots: 64 token-pairs x 8 d-quads
        int tp = s >> 3;
        int d4 = (s & 7) << 2;
        int t0 = 2 * tp, t1 = 2 * tp + 1;
        ushort h0[4] = {0, 0, 0, 0}, h1[4] = {0, 0, 0, 0};
        ushort l0[4] = {0, 0, 0, 0}, l1[4] = {0, 0, 0, 0};
        if (t0 < N_TOK) {
            size_t base = ((size_t)(b * N_TOK + t0)) * QKV_N + 2 * C_DIM + h * HD + d4;
            *reinterpret_cast<ushort4*>(h0) = *reinterpret_cast<const ushort4*>(g_qkv_hi + base);
            *reinterpret_cast<ushort4*>(l0) = *reinterpret_cast<const ushort4*>(g_qkv_lo + base);
        }
        if (t1 < N_TOK) {
            size_t base = ((size_t)(b * N_TOK + t1)) * QKV_N + 2 * C_DIM + h * HD + d4;
            *reinterpret_cast<ushort4*>(h1) = *reinterpret_cast<const ushort4*>(g_qkv_hi + base);
            *reinterpret_cast<ushort4*>(l1) = *reinterpret_cast<const ushort4*>(g_qkv_lo + base);
        }
#pragma unroll
        for (int d = 0; d < 4; d++) {
            uint32_t hi = (uint32_t)h0[d] | ((uint32_t)h1[d] << 16);
            uint32_t lo = (uint32_t)l0[d] | ((uint32_t)l1[d] << 16);
            *reinterpret_cast<uint32_t*>(vt + (d4 + d) * VRB + tp * 4)        = hi;
            *reinterpret_cast<uint32_t*>(vt + VREG + (d4 + d) * VRB + tp * 4) = lo;
        }
    }
    __syncthreads();

    // ---- phase 1: S = q k^T via mma (ldmatrix fragments) ----
    const int wm = (wid >> 1) * 32;
    const int wn = (wid & 1) * 64;
    const int wpair = wid & 1;
    float acc[2][8][4];
#pragma unroll
    for (int mt = 0; mt < 2; mt++)
#pragma unroll
        for (int q = 0; q < 8; q++)
#pragma unroll
            for (int j = 0; j < 4; j++) acc[mt][q][j] = 0.f;
    compute_chunk_l(sb, wm, wn, lane, acc);

    // ---- phase 2: add bias+mask (float2); pad = -1e9 ----
    {
        const float* bp = g_bias + (size_t)h * (N_TOK * N_TOK);
        const float* mp = mask + (size_t)(b & (NW - 1)) * (N_TOK * N_TOK);
#pragma unroll
        for (int mt = 0; mt < 2; mt++) {
            int rr0 = wm + mt * 16 + g;
            int rr1 = rr0 + 8;
#pragma unroll
            for (int q = 0; q < 8; q++) {
                int cc = wn + q * 8 + 2 * t;
                if (cc < N_TOK && rr0 < N_TOK) {
                    float2 bb = *reinterpret_cast<const float2*>(bp + rr0 * N_TOK + cc);
                    float2 mm = *reinterpret_cast<const float2*>(mp + rr0 * N_TOK + cc);
                    acc[mt][q][0] += bb.x + mm.x;
                    acc[mt][q][1] += bb.y + mm.y;
                } else {
                    acc[mt][q][0] = -1e9f;
                    acc[mt][q][1] = -1e9f;
                }
                if (cc < N_TOK && rr1 < N_TOK) {
                    float2 bb = *reinterpret_cast<const float2*>(bp + rr1 * N_TOK + cc);
                    float2 mm = *reinterpret_cast<const float2*>(mp + rr1 * N_TOK + cc);
                    acc[mt][q][2] += bb.x + mm.x;
                    acc[mt][q][3] += bb.y + mm.y;
                } else {
                    acc[mt][q][2] = -1e9f;
                    acc[mt][q][3] = -1e9f;
                }
            }
        }
    }

    // ---- phase 3: register softmax ----
#pragma unroll
    for (int mt = 0; mt < 2; mt++) {
        float m0 = -1e30f, m1 = -1e30f;
#pragma unroll
        for (int q = 0; q < 8; q++) {
            m0 = fmaxf(m0, fmaxf(acc[mt][q][0], acc[mt][q][1]));
            m1 = fmaxf(m1, fmaxf(acc[mt][q][2], acc[mt][q][3]));
        }
#pragma unroll
        for (int off = 1; off <= 2; off <<= 1) {
            m0 = fmaxf(m0, __shfl_xor_sync(0xFFFFFFFFu, m0, off));
            m1 = fmaxf(m1, __shfl_xor_sync(0xFFFFFFFFu, m1, off));
        }
        if (t == 0) {
            redM[wpair * PM + wm + mt * 16 + g]     = m0;
            redM[wpair * PM + wm + mt * 16 + g + 8] = m1;
        }
    }
    __syncthreads();

#pragma unroll
    for (int mt = 0; mt < 2; mt++) {
        int r0 = wm + mt * 16 + g;
        float M0 = fmaxf(redM[r0], redM[PM + r0]);
        float M1 = fmaxf(redM[r0 + 8], redM[PM + r0 + 8]);
        float s0 = 0.f, s1 = 0.f;
#pragma unroll
        for (int q = 0; q < 8; q++) {
            float e0 = __expf(acc[mt][q][0] - M0);
            float e1 = __expf(acc[mt][q][1] - M0);
            float e2 = __expf(acc[mt][q][2] - M1);
            float e3 = __expf(acc[mt][q][3] - M1);
            acc[mt][q][0] = e0; acc[mt][q][1] = e1;
            acc[mt][q][2] = e2; acc[mt][q][3] = e3;
            s0 += e0 + e1;
            s1 += e2 + e3;
        }
#pragma unroll
        for (int off = 1; off <= 2; off <<= 1) {
            s0 += __shfl_xor_sync(0xFFFFFFFFu, s0, off);
            s1 += __shfl_xor_sync(0xFFFFFFFFu, s1, off);
        }
        if (t == 0) {
            redS[wpair * PM + r0]     = s0;
            redS[wpair * PM + r0 + 8] = s1;
        }
    }
    __syncthreads();   // also fences qk reads (done) vs Pz writes below

    // normalize + write P split bf16 hi/lo directly into Pz
#pragma unroll
    for (int mt = 0; mt < 2; mt++) {
        int r0 = wm + mt * 16 + g;
        float inv0 = 1.f / (redS[r0] + redS[PM + r0]);
        float inv1 = 1.f / (redS[r0 + 8] + redS[PM + r0 + 8]);
#pragma unroll
        for (int q = 0; q < 8; q++) {
            int cc = wn + q * 8 + 2 * t;
            uint32_t hi, lo;
            split2(acc[mt][q][0] * inv0, acc[mt][q][1] * inv0, hi, lo);
            *reinterpret_cast<uint32_t*>(Pz + r0 * PRB + cc * 2)        = hi;
            *reinterpret_cast<uint32_t*>(Pz + PREG + r0 * PRB + cc * 2) = lo;
            split2(acc[mt][q][2] * inv1, acc[mt][q][3] * inv1, hi, lo);
            *reinterpret_cast<uint32_t*>(Pz + (r0 + 8) * PRB + cc * 2)        = hi;
            *reinterpret_cast<uint32_t*>(Pz + PREG + (r0 + 8) * PRB + cc * 2) = lo;
        }
    }
    __syncthreads();

    // ---- phase 4: O = P V via mma (ldmatrix fragments) ----
    const int wn2 = (wid & 1) * 16;
    const int arow  = lane & 15;
    const int acol2 = ((lane >> 4) << 3) * 2;
    const int brow  = (lane & 7) + ((lane >> 3) & 2) * 4;
    const int bcol2 = (((lane >> 3) & 1) << 3) * 2;
    float oacc[2][2][4];
#pragma unroll
    for (int mt = 0; mt < 2; mt++)
#pragma unroll
        for (int q = 0; q < 2; q++)
#pragma unroll
            for (int j = 0; j < 4; j++) oacc[mt][q][j] = 0.f;

#pragma unroll
    for (int kc = 0; kc < 8; kc++) {
        const int ks = kc * 16;
        uint32_t ah[2][4], al[2][4];
#pragma unroll
        for (int mt = 0; mt < 2; mt++) {
            uint32_t aaddr = sb + (wm + mt * 16 + arow) * PRB + ks * 2 + acol2;
            ldsm4(ah[mt], aaddr);
            ldsm4(al[mt], aaddr + PREG);
        }
        uint32_t baddr = sb + OFF_VT + (wn2 + brow) * VRB + ks * 2 + bcol2;
        uint32_t bh[4], bl[4];
        ldsm4(bh, baddr);
        ldsm4(bl, baddr + VREG);
#pragma unroll
        for (int hf = 0; hf < 2; hf++)
#pragma unroll
            for (int mt = 0; mt < 2; mt++)
                mma16816(oacc[mt][hf], ah[mt], bh + 2 * hf);
#pragma unroll
        for (int hf = 0; hf < 2; hf++)
#pragma unroll
            for (int mt = 0; mt < 2; mt++)
                mma16816(oacc[mt][hf], ah[mt], bl + 2 * hf);
#pragma unroll
        for (int hf = 0; hf < 2; hf++)
#pragma unroll
            for (int mt = 0; mt < 2; mt++)
                mma16816(oacc[mt][hf], al[mt], bh + 2 * hf);
    }

    // ---- phase 5: write O rows < 98 as split bf16 hi/lo ----
#pragma unroll
    for (int mt = 0; mt < 2; mt++) {
#pragma unroll
        for (int q = 0; q < 2; q++) {
            int rr = wm + mt * 16 + g;
            int cc = h * HD + wn2 + q * 8 + 2 * t;
            uint32_t hi, lo;
            if (rr < N_TOK) {
                size_t o = (size_t)(b * N_TOK + rr) * C_DIM + cc;
                split2(oacc[mt][q][0], oacc[mt][q][1], hi, lo);
                *reinterpret_cast<uint32_t*>(g_att_hi + o) = hi;
                *reinterpret_cast<uint32_t*>(g_att_lo + o) = lo;
            }
            if (rr + 8 < N_TOK) {
                size_t o = (size_t)(b * N_TOK + rr + 8) * C_DIM + cc;
                split2(oacc[mt][q][2], oacc[mt][q][3], hi, lo);
                *reinterpret_cast<uint32_t*>(g_att_hi + o) = hi;
                *reinterpret_cast<uint32_t*>(g_att_lo + o) = lo;
            }
        }
    }
}

// ---------------------------------------------------------------
// Launch
// ---------------------------------------------------------------
extern "C" void kernel_launch(void* const* d_in, const int* in_sizes, int n_in,
                              void* d_out, int out_size) {
    const float* x          = (const float*)d_in[0];
    const float* mask       = (const float*)d_in[1];
    const float* qkv_w      = (const float*)d_in[2];
    const float* qkv_b      = (const float*)d_in[3];
    const float* proj_w     = (const float*)d_in[4];
    const float* proj_b     = (const float*)d_in[5];
    const float* bias_table = (const float*)d_in[6];
    const int*   rel_index  = (const int*)d_in[7];
    float* out = (float*)d_out;

    cudaFuncSetAttribute(attn_hmma_kernel,
                         cudaFuncAttributeMaxDynamicSharedMemorySize, ATTN_SMEM);
    const int gemm_smem = 2 * BUF_B;   // 81920
    cudaFuncSetAttribute(qkv_gemm_kernel,
                         cudaFuncAttributeMaxDynamicSharedMemorySize, gemm_smem);
    cudaFuncSetAttribute(proj_gemm_kernel,
                         cudaFuncAttributeMaxDynamicSharedMemorySize, gemm_smem);

    // 0) presplit weights (1 MB, ~10us)
    presplit_w_kernel<<<256, 256>>>(qkv_w, proj_w);
    // 1) bias gather
    {
        int total = H_NUM * N_TOK * N_TOK;
        gather_bias_kernel<<<(total + 255) / 256, 256>>>(bias_table, rel_index);
    }
    // 2) QKV projection (HMMA bf16x3, split output + q pre-scale)
    {
        dim3 grid(QKV_N / 128, M_ROWS / 128);
        qkv_gemm_kernel<<<grid, 256, gemm_smem>>>(x, qkv_b);
    }
    // 3) HMMA attention per (b,h), register softmax
    {
        attn_hmma_kernel<<<B_TOT * H_NUM, 256, ATTN_SMEM>>>(mask);
    }
    // 4) output projection (HMMA bf16x3, fp32 output)
    {
        dim3 grid(C_DIM / 128, M_ROWS / 128);
        proj_gemm_kernel<<<grid, 256, gemm_smem>>>(proj_b, out);
    }
}

// round 14
// speedup vs baseline: 1.2367x; 1.2367x over previous
#include <cuda_runtime.h>
#include <cuda_bf16.h>
#include <cstdint>

// Problem constants
#define B_TOT   2048
#define N_TOK   98
#define C_DIM   256
#define H_NUM   8
#define HD      32
#define NW      512
#define M_ROWS  (B_TOT * N_TOK)          // 200704
#define QKV_N   (3 * C_DIM)              // 768

// -------- scratch (static device globals; device-code refs ONLY) --------
__device__ float g_qkv[(size_t)M_ROWS * QKV_N];   // fp32 (R11-proven IO)
__device__ float g_att[(size_t)M_ROWS * C_DIM];
__device__ float g_bias[H_NUM * N_TOK * N_TOK];

// ================= helpers =================
__device__ __forceinline__ uint32_t smem_u32(const void* p) {
    uint32_t a;
    asm("{ .reg .u64 t; cvta.to.shared.u64 t, %1; cvt.u32.u64 %0, t; }"
        : "=r"(a) : "l"(p));
    return a;
}

__device__ __forceinline__ void mma16816(float* c, const uint32_t* a, const uint32_t* b) {
    asm volatile(
        "mma.sync.aligned.m16n8k16.row.col.f32.bf16.bf16.f32 "
        "{%0,%1,%2,%3}, {%4,%5,%6,%7}, {%8,%9}, {%0,%1,%2,%3};"
        : "+f"(c[0]), "+f"(c[1]), "+f"(c[2]), "+f"(c[3])
        : "r"(a[0]), "r"(a[1]), "r"(a[2]), "r"(a[3]), "r"(b[0]), "r"(b[1]));
}

__device__ __forceinline__ void ldsm4(uint32_t* r, uint32_t addr) {
    asm volatile("ldmatrix.sync.aligned.m8n8.x4.shared.b16 {%0,%1,%2,%3}, [%4];"
                 : "=r"(r[0]), "=r"(r[1]), "=r"(r[2]), "=r"(r[3]) : "r"(addr));
}

__device__ __forceinline__ void split2(float x, float y, uint32_t& hi, uint32_t& lo) {
    __nv_bfloat16 hx = __float2bfloat16(x);
    __nv_bfloat16 hy = __float2bfloat16(y);
    __nv_bfloat16 lx = __float2bfloat16(x - __bfloat162float(hx));
    __nv_bfloat16 ly = __float2bfloat16(y - __bfloat162float(hy));
    hi = (uint32_t)__bfloat16_as_ushort(hx) | ((uint32_t)__bfloat16_as_ushort(hy) << 16);
    lo = (uint32_t)__bfloat16_as_ushort(lx) | ((uint32_t)__bfloat16_as_ushort(ly) << 16);
}

__device__ __forceinline__ uint32_t lds32(const char* p) {
    return *reinterpret_cast<const uint32_t*>(p);
}

// ---------------------------------------------------------------
// Kernel 1: gather relative-position bias  -> g_bias[h][n][m]
// ---------------------------------------------------------------
__global__ void gather_bias_kernel(const float* __restrict__ table,
                                   const int* __restrict__ rel) {
    int idx = blockIdx.x * blockDim.x + threadIdx.x;
    const int total = H_NUM * N_TOK * N_TOK;
    if (idx < total) {
        int h  = idx / (N_TOK * N_TOK);
        int nm = idx % (N_TOK * N_TOK);
        g_bias[idx] = table[rel[nm] * H_NUM + h];
    }
}

// ---------------------------------------------------------------
// HMMA bf16x3 split GEMM (R11 verbatim — proven 808/262 us)
// ---------------------------------------------------------------
#define RB    80          // row bytes (40 halves)
#define REG_B 10240       // region bytes
#define BUF_B 40960       // buffer bytes

__device__ __forceinline__ void ld_chunk(const float* __restrict__ A,
                                         const float* __restrict__ W,
                                         int m0, int n0, int k0, int tid,
                                         float4* r) {
#pragma unroll
    for (int i = 0; i < 4; i++) {
        int f4  = tid + i * 256;
        int row = f4 >> 3;
        int c4  = (f4 & 7) << 2;
        r[i]     = *reinterpret_cast<const float4*>(A + (size_t)(m0 + row) * C_DIM + k0 + c4);
        r[4 + i] = *reinterpret_cast<const float4*>(W + (size_t)(n0 + row) * C_DIM + k0 + c4);
    }
}

__device__ __forceinline__ void st_chunk(char* buf, int tid, const float4* r) {
#pragma unroll
    for (int i = 0; i < 4; i++) {
        int f4  = tid + i * 256;
        int row = f4 >> 3;
        int c4  = (f4 & 7) << 2;
        int off = row * RB + c4 * 2;
        uint32_t h01, l01, h23, l23;
        split2(r[i].x, r[i].y, h01, l01);
        split2(r[i].z, r[i].w, h23, l23);
        *reinterpret_cast<uint2*>(buf + off)         = make_uint2(h01, h23);
        *reinterpret_cast<uint2*>(buf + REG_B + off) = make_uint2(l01, l23);
        split2(r[4 + i].x, r[4 + i].y, h01, l01);
        split2(r[4 + i].z, r[4 + i].w, h23, l23);
        *reinterpret_cast<uint2*>(buf + 2 * REG_B + off) = make_uint2(h01, h23);
        *reinterpret_cast<uint2*>(buf + 3 * REG_B + off) = make_uint2(l01, l23);
    }
}

__device__ __forceinline__ void compute_chunk_s(const char* sbuf, int wm, int wn,
                                                int lane, float acc[2][8][4]) {
    const int g = lane >> 2;
    const int t = lane & 3;
#pragma unroll
    for (int ks = 0; ks < 32; ks += 16) {
        uint32_t ah[2][4], al[2][4];
#pragma unroll
        for (int mt = 0; mt < 2; mt++) {
            const char* a0p = sbuf + (wm + mt * 16 + g) * RB + (ks + 2 * t) * 2;
            ah[mt][0] = lds32(a0p);
            ah[mt][1] = lds32(a0p + 8 * RB);
            ah[mt][2] = lds32(a0p + 16);
            ah[mt][3] = lds32(a0p + 8 * RB + 16);
            al[mt][0] = lds32(a0p + REG_B);
            al[mt][1] = lds32(a0p + REG_B + 8 * RB);
            al[mt][2] = lds32(a0p + REG_B + 16);
            al[mt][3] = lds32(a0p + REG_B + 8 * RB + 16);
        }
#pragma unroll
        for (int qh = 0; qh < 2; qh++) {
            uint32_t bh[4][2], bl[4][2];
#pragma unroll
            for (int q4 = 0; q4 < 4; q4++) {
                const char* b0p = sbuf + 2 * REG_B
                    + (wn + (qh * 4 + q4) * 8 + g) * RB + (ks + 2 * t) * 2;
                bh[q4][0] = lds32(b0p);
                bh[q4][1] = lds32(b0p + 16);
                bl[q4][0] = lds32(b0p + REG_B);
                bl[q4][1] = lds32(b0p + REG_B + 16);
            }
#pragma unroll
            for (int q4 = 0; q4 < 4; q4++)
#pragma unroll
                for (int mt = 0; mt < 2; mt++)
                    mma16816(acc[mt][qh * 4 + q4], ah[mt], bh[q4]);
#pragma unroll
            for (int q4 = 0; q4 < 4; q4++)
#pragma unroll
                for (int mt = 0; mt < 2; mt++)
                    mma16816(acc[mt][qh * 4 + q4], ah[mt], bl[q4]);
#pragma unroll
            for (int q4 = 0; q4 < 4; q4++)
#pragma unroll
                for (int mt = 0; mt < 2; mt++)
                    mma16816(acc[mt][qh * 4 + q4], al[mt], bh[q4]);
        }
    }
}

__device__ __forceinline__ void hgemm_body(char* smem,
                                           const float* __restrict__ A,
                                           const float* __restrict__ W,
                                           const float* __restrict__ bias,
                                           float* __restrict__ C, int Ntot) {
    const int tid  = threadIdx.x;
    const int wid  = tid >> 5;
    const int lane = tid & 31;
    const int m0 = blockIdx.y * 128;
    const int n0 = blockIdx.x * 128;
    const int wm = (wid >> 1) * 32;
    const int wn = (wid & 1) * 64;

    float acc[2][8][4];
#pragma unroll
    for (int mt = 0; mt < 2; mt++)
#pragma unroll
        for (int nt = 0; nt < 8; nt++)
#pragma unroll
            for (int j = 0; j < 4; j++) acc[mt][nt][j] = 0.f;

    float4 pref[8];
    ld_chunk(A, W, m0, n0, 0, tid, pref);
    st_chunk(smem, tid, pref);
    __syncthreads();

#pragma unroll 1
    for (int ch = 0; ch < 8; ch++) {
        if (ch < 7) ld_chunk(A, W, m0, n0, (ch + 1) * 32, tid, pref);
        compute_chunk_s(smem + (ch & 1) * BUF_B, wm, wn, lane, acc);
        if (ch < 7) st_chunk(smem + ((ch + 1) & 1) * BUF_B, tid, pref);
        __syncthreads();
    }

    const int g = lane >> 2;
    const int t = lane & 3;
#pragma unroll
    for (int mt = 0; mt < 2; mt++) {
#pragma unroll
        for (int q = 0; q < 8; q++) {
            int rr = m0 + wm + mt * 16 + g;
            int cc = n0 + wn + q * 8 + 2 * t;
            float b0 = bias[cc], b1 = bias[cc + 1];
            float2 v0 = make_float2(acc[mt][q][0] + b0, acc[mt][q][1] + b1);
            float2 v1 = make_float2(acc[mt][q][2] + b0, acc[mt][q][3] + b1);
            *reinterpret_cast<float2*>(C + (size_t)rr * Ntot + cc)       = v0;
            *reinterpret_cast<float2*>(C + (size_t)(rr + 8) * Ntot + cc) = v1;
        }
    }
}

__global__ void __launch_bounds__(256, 2)
qkv_gemm_kernel(const float* __restrict__ x, const float* __restrict__ w,
                const float* __restrict__ b) {
    extern __shared__ char smem[];
    hgemm_body(smem, x, w, b, g_qkv, QKV_N);
}

__global__ void __launch_bounds__(256, 2)
proj_gemm_kernel(const float* __restrict__ w, const float* __restrict__ b,
                 float* __restrict__ out) {
    extern __shared__ char smem[];
    hgemm_body(smem, g_att, w, b, out, C_DIM);
}

// ---------------------------------------------------------------
// Kernel 3: HMMA attention, 8x1 warp layout, P kept in registers.
// Each warp owns 16 full rows x 128 cols (acc[16][4]); softmax is
// warp-local (quad shfl); PV builds A fragments from registers.
// smem = qk 40960 + vt 17408 = 58368; ONE __syncthreads total.
// ---------------------------------------------------------------
#define VRB   272
#define VREG  (HD * VRB)          // 8704
#define OFF_VT   (4 * REG_B)            // 40960
#define ATTN_SMEM (OFF_VT + 2 * VREG)   // 58368

__global__ void __launch_bounds__(256, 2)
attn_hmma_kernel(const float* __restrict__ mask) {
    extern __shared__ char smem[];
    const int tid  = threadIdx.x;
    const int wid  = tid >> 5;
    const int lane = tid & 31;
    const int g = lane >> 2;
    const int t = lane & 3;
    const int bh = blockIdx.x;
    const int b  = bh >> 3;
    const int h  = bh & 7;
    const float scale = 0.17677669529663687f;   // 1/sqrt(32)

    char*  qk = smem;                    // q hi/lo, k hi/lo (RB=80)
    char*  vt = smem + OFF_VT;
    const uint32_t sb = smem_u32(smem);

    // ---- phase 0: load q (scaled), k from fp32 g_qkv; split; V^T ----
#pragma unroll
    for (int i = 0; i < 4; i++) {
        int s = tid + 256 * i;          // 1024 slots: 128 rows x 8 quads
        int row = s >> 3;
        int c4  = (s & 7) << 2;
        float4 qv = make_float4(0.f, 0.f, 0.f, 0.f);
        float4 kv = qv;
        if (row < N_TOK) {
            size_t base = ((size_t)(b * N_TOK + row)) * QKV_N + h * HD + c4;
            qv = *reinterpret_cast<const float4*>(g_qkv + base);
            kv = *reinterpret_cast<const float4*>(g_qkv + base + C_DIM);
            qv.x *= scale; qv.y *= scale; qv.z *= scale; qv.w *= scale;
        }
        int off = row * RB + c4 * 2;
        uint32_t h01, l01, h23, l23;
        split2(qv.x, qv.y, h01, l01);
        split2(qv.z, qv.w, h23, l23);
        *reinterpret_cast<uint2*>(qk + off)             = make_uint2(h01, h23);
        *reinterpret_cast<uint2*>(qk + REG_B + off)     = make_uint2(l01, l23);
        split2(kv.x, kv.y, h01, l01);
        split2(kv.z, kv.w, h23, l23);
        *reinterpret_cast<uint2*>(qk + 2 * REG_B + off) = make_uint2(h01, h23);
        *reinterpret_cast<uint2*>(qk + 3 * REG_B + off) = make_uint2(l01, l23);
    }
    // V^T: vt[d][token-pair] bf16 hi/lo
#pragma unroll
    for (int i = 0; i < 2; i++) {
        int s  = tid + 256 * i;          // 512 slots: 64 token-pairs x 8 d-quads
        int tp = s >> 3;
        int d4 = (s & 7) << 2;
        int t0 = 2 * tp, t1 = 2 * tp + 1;
        float4 v0 = make_float4(0.f, 0.f, 0.f, 0.f), v1 = v0;
        if (t0 < N_TOK)
            v0 = *reinterpret_cast<const float4*>(
                g_qkv + ((size_t)(b * N_TOK + t0)) * QKV_N + 2 * C_DIM + h * HD + d4);
        if (t1 < N_TOK)
            v1 = *reinterpret_cast<const float4*>(
                g_qkv + ((size_t)(b * N_TOK + t1)) * QKV_N + 2 * C_DIM + h * HD + d4);
        float e0[4] = { v0.x, v0.y, v0.z, v0.w };
        float e1[4] = { v1.x, v1.y, v1.z, v1.w };
#pragma unroll
        for (int d = 0; d < 4; d++) {
            uint32_t hi, lo;
            split2(e0[d], e1[d], hi, lo);
            *reinterpret_cast<uint32_t*>(vt + (d4 + d) * VRB + tp * 4)        = hi;
            *reinterpret_cast<uint32_t*>(vt + VREG + (d4 + d) * VRB + tp * 4) = lo;
        }
    }
    __syncthreads();   // THE only block-wide sync

    // ---- phase 1: S = q k^T. Warp wid owns rows [wm, wm+16). ----
    const int wm = wid * 16;
    const int arow  = lane & 15;
    const int acol2 = ((lane >> 4) << 3) * 2;
    const int brow  = (lane & 7) + ((lane >> 3) & 2) * 4;
    const int bcol2 = (((lane >> 3) & 1) << 3) * 2;

    float acc[16][4];
#pragma unroll
    for (int q = 0; q < 16; q++)
#pragma unroll
        for (int j = 0; j < 4; j++) acc[q][j] = 0.f;

#pragma unroll
    for (int ks = 0; ks < 32; ks += 16) {
        uint32_t ah[4], al[4];
        uint32_t aaddr = sb + (wm + arow) * RB + ks * 2 + acol2;
        ldsm4(ah, aaddr);
        ldsm4(al, aaddr + REG_B);
#pragma unroll
        for (int qp = 0; qp < 8; qp++) {
            uint32_t baddr = sb + 2 * REG_B + (qp * 16 + brow) * RB + ks * 2 + bcol2;
            uint32_t bh[4], bl[4];
            ldsm4(bh, baddr);
            ldsm4(bl, baddr + REG_B);
#pragma unroll
            for (int hf = 0; hf < 2; hf++)
                mma16816(acc[qp * 2 + hf], ah, bh + 2 * hf);
#pragma unroll
            for (int hf = 0; hf < 2; hf++)
                mma16816(acc[qp * 2 + hf], ah, bl + 2 * hf);
#pragma unroll
            for (int hf = 0; hf < 2; hf++)
                mma16816(acc[qp * 2 + hf], al, bh + 2 * hf);
        }
    }

    // ---- phase 2: add bias + mask; pad cells = -1e9 ----
    {
        const float* bp = g_bias + (size_t)h * (N_TOK * N_TOK);
        const float* mp = mask + (size_t)(b & (NW - 1)) * (N_TOK * N_TOK);
        const int rr0 = wm + g;
        const int rr1 = rr0 + 8;
#pragma unroll
        for (int q = 0; q < 16; q++) {
            int cc = q * 8 + 2 * t;
            if (cc < N_TOK && rr0 < N_TOK) {
                float2 bb = *reinterpret_cast<const float2*>(bp + rr0 * N_TOK + cc);
                float2 mm = *reinterpret_cast<const float2*>(mp + rr0 * N_TOK + cc);
                acc[q][0] += bb.x + mm.x;
                acc[q][1] += bb.y + mm.y;
            } else {
                acc[q][0] = -1e9f;
                acc[q][1] = -1e9f;
            }
            if (cc < N_TOK && rr1 < N_TOK) {
                float2 bb = *reinterpret_cast<const float2*>(bp + rr1 * N_TOK + cc);
                float2 mm = *reinterpret_cast<const float2*>(mp + rr1 * N_TOK + cc);
                acc[q][2] += bb.x + mm.x;
                acc[q][3] += bb.y + mm.y;
            } else {
                acc[q][2] = -1e9f;
                acc[q][3] = -1e9f;
            }
        }
    }

    // ---- phase 3: warp-local softmax (rows entirely in quad) ----
    float inv0, inv1;
    {
        float m0 = -1e30f, m1 = -1e30f;
#pragma unroll
        for (int q = 0; q < 16; q++) {
            m0 = fmaxf(m0, fmaxf(acc[q][0], acc[q][1]));
            m1 = fmaxf(m1, fmaxf(acc[q][2], acc[q][3]));
        }
#pragma unroll
        for (int off = 1; off <= 2; off <<= 1) {
            m0 = fmaxf(m0, __shfl_xor_sync(0xFFFFFFFFu, m0, off));
            m1 = fmaxf(m1, __shfl_xor_sync(0xFFFFFFFFu, m1, off));
        }
        float s0 = 0.f, s1 = 0.f;
#pragma unroll
        for (int q = 0; q < 16; q++) {
            float e0 = __expf(acc[q][0] - m0);
            float e1 = __expf(acc[q][1] - m0);
            float e2 = __expf(acc[q][2] - m1);
            float e3 = __expf(acc[q][3] - m1);
            acc[q][0] = e0; acc[q][1] = e1;
            acc[q][2] = e2; acc[q][3] = e3;
            s0 += e0 + e1;
            s1 += e2 + e3;
        }
#pragma unroll
        for (int off = 1; off <= 2; off <<= 1) {
            s0 += __shfl_xor_sync(0xFFFFFFFFu, s0, off);
            s1 += __shfl_xor_sync(0xFFFFFFFFu, s1, off);
        }
        inv0 = 1.f / s0;
        inv1 = 1.f / s1;
    }

    // ---- phase 4: O = P~ V via mma; A fragments built from registers ----
    float oacc[4][4];
#pragma unroll
    for (int nt = 0; nt < 4; nt++)
#pragma unroll
        for (int j = 0; j < 4; j++) oacc[nt][j] = 0.f;

#pragma unroll
    for (int kc = 0; kc < 8; kc++) {
        uint32_t ah[4], al[4];
        split2(acc[2 * kc][0],     acc[2 * kc][1],     ah[0], al[0]);
        split2(acc[2 * kc][2],     acc[2 * kc][3],     ah[1], al[1]);
        split2(acc[2 * kc + 1][0], acc[2 * kc + 1][1], ah[2], al[2]);
        split2(acc[2 * kc + 1][2], acc[2 * kc + 1][3], ah[3], al[3]);
#pragma unroll
        for (int np = 0; np < 2; np++) {
            uint32_t baddr = sb + OFF_VT + (np * 16 + brow) * VRB + kc * 32 + bcol2;
            uint32_t bh[4], bl[4];
            ldsm4(bh, baddr);
            ldsm4(bl, baddr + VREG);
#pragma unroll
            for (int hf = 0; hf < 2; hf++) {
                int nt = np * 2 + hf;
                mma16816(oacc[nt], ah, bh + 2 * hf);
                mma16816(oacc[nt], ah, bl + 2 * hf);
                mma16816(oacc[nt], al, bh + 2 * hf);
            }
        }
    }

    // ---- phase 5: normalize + write O (fp32 g_att), rows < 98 ----
    {
        const int rr0 = wm + g;
        const int rr1 = rr0 + 8;
#pragma unroll
        for (int nt = 0; nt < 4; nt++) {
            int cc = h * HD + nt * 8 + 2 * t;
            if (rr0 < N_TOK)
                *reinterpret_cast<float2*>(g_att + (size_t)(b * N_TOK + rr0) * C_DIM + cc)
                    = make_float2(oacc[nt][0] * inv0, oacc[nt][1] * inv0);
            if (rr1 < N_TOK)
                *reinterpret_cast<float2*>(g_att + (size_t)(b * N_TOK + rr1) * C_DIM + cc)
                    = make_float2(oacc[nt][2] * inv1, oacc[nt][3] * inv1);
        }
    }
}

// ---------------------------------------------------------------
// Launch
// ---------------------------------------------------------------
extern "C" void kernel_launch(void* const* d_in, const int* in_sizes, int n_in,
                              void* d_out, int out_size) {
    const float* x          = (const float*)d_in[0];
    const float* mask       = (const float*)d_in[1];
    const float* qkv_w      = (const float*)d_in[2];
    const float* qkv_b      = (const float*)d_in[3];
    const float* proj_w     = (const float*)d_in[4];
    const float* proj_b     = (const float*)d_in[5];
    const float* bias_table = (const float*)d_in[6];
    const int*   rel_index  = (const int*)d_in[7];
    float* out = (float*)d_out;

    cudaFuncSetAttribute(attn_hmma_kernel,
                         cudaFuncAttributeMaxDynamicSharedMemorySize, ATTN_SMEM);
    const int gemm_smem = 2 * BUF_B;   // 81920
    cudaFuncSetAttribute(qkv_gemm_kernel,
                         cudaFuncAttributeMaxDynamicSharedMemorySize, gemm_smem);
    cudaFuncSetAttribute(proj_gemm_kernel,
                         cudaFuncAttributeMaxDynamicSharedMemorySize, gemm_smem);

    // 1) bias gather
    {
        int total = H_NUM * N_TOK * N_TOK;
        gather_bias_kernel<<<(total + 255) / 256, 256>>>(bias_table, rel_index);
    }
    // 2) QKV projection (HMMA bf16x3): [200704,256] x [768,256]^T -> g_qkv
    {
        dim3 grid(QKV_N / 128, M_ROWS / 128);
        qkv_gemm_kernel<<<grid, 256, gemm_smem>>>(x, qkv_w, qkv_b);
    }
    // 3) HMMA attention per (b,h), register P + warp-local softmax
    {
        attn_hmma_kernel<<<B_TOT * H_NUM, 256, ATTN_SMEM>>>(mask);
    }
    // 4) output projection (HMMA bf16x3): [200704,256] x [256,256]^T -> d_out
    {
        dim3 grid(C_DIM / 128, M_ROWS / 128);
        proj_gemm_kernel<<<grid, 256, gemm_smem>>>(proj_w, proj_b, out);
    }
}

// round 15
// speedup vs baseline: 1.2454x; 1.0070x over previous
#include <cuda_runtime.h>
#include <cuda_bf16.h>
#include <cstdint>

// Problem constants
#define B_TOT   2048
#define N_TOK   98
#define C_DIM   256
#define H_NUM   8
#define HD      32
#define NW      512
#define M_ROWS  (B_TOT * N_TOK)          // 200704
#define QKV_N   (3 * C_DIM)              // 768

// -------- scratch (static device globals; device-code refs ONLY) --------
__device__ float g_qkv[(size_t)M_ROWS * QKV_N];
__device__ float g_att[(size_t)M_ROWS * C_DIM];
__device__ float g_bias[H_NUM * N_TOK * N_TOK];

// ================= helpers =================
__device__ __forceinline__ uint32_t smem_u32(const void* p) {
    uint32_t a;
    asm("{ .reg .u64 t; cvta.to.shared.u64 t, %1; cvt.u32.u64 %0, t; }"
        : "=r"(a) : "l"(p));
    return a;
}

__device__ __forceinline__ void mma16816(float* c, const uint32_t* a, const uint32_t* b) {
    asm volatile(
        "mma.sync.aligned.m16n8k16.row.col.f32.bf16.bf16.f32 "
        "{%0,%1,%2,%3}, {%4,%5,%6,%7}, {%8,%9}, {%0,%1,%2,%3};"
        : "+f"(c[0]), "+f"(c[1]), "+f"(c[2]), "+f"(c[3])
        : "r"(a[0]), "r"(a[1]), "r"(a[2]), "r"(a[3]), "r"(b[0]), "r"(b[1]));
}

__device__ __forceinline__ void ldsm4(uint32_t* r, uint32_t addr) {
    asm volatile("ldmatrix.sync.aligned.m8n8.x4.shared.b16 {%0,%1,%2,%3}, [%4];"
                 : "=r"(r[0]), "=r"(r[1]), "=r"(r[2]), "=r"(r[3]) : "r"(addr));
}

__device__ __forceinline__ void split2(float x, float y, uint32_t& hi, uint32_t& lo) {
    __nv_bfloat16 hx = __float2bfloat16(x);
    __nv_bfloat16 hy = __float2bfloat16(y);
    __nv_bfloat16 lx = __float2bfloat16(x - __bfloat162float(hx));
    __nv_bfloat16 ly = __float2bfloat16(y - __bfloat162float(hy));
    hi = (uint32_t)__bfloat16_as_ushort(hx) | ((uint32_t)__bfloat16_as_ushort(hy) << 16);
    lo = (uint32_t)__bfloat16_as_ushort(lx) | ((uint32_t)__bfloat16_as_ushort(ly) << 16);
}

__device__ __forceinline__ uint32_t lds32(const char* p) {
    return *reinterpret_cast<const uint32_t*>(p);
}

// ---------------------------------------------------------------
// Kernel 1: gather relative-position bias  -> g_bias[h][n][m]
// ---------------------------------------------------------------
__global__ void gather_bias_kernel(const float* __restrict__ table,
                                   const int* __restrict__ rel) {
    int idx = blockIdx.x * blockDim.x + threadIdx.x;
    const int total = H_NUM * N_TOK * N_TOK;
    if (idx < total) {
        int h  = idx / (N_TOK * N_TOK);
        int nm = idx % (N_TOK * N_TOK);
        g_bias[idx] = table[rel[nm] * H_NUM + h];
    }
}

// ---------------------------------------------------------------
// HMMA bf16x3 split GEMM (R14/R11 verbatim — proven 808/262 us)
// ---------------------------------------------------------------
#define RB    80          // row bytes (40 halves)
#define REG_B 10240       // region bytes
#define BUF_B 40960       // buffer bytes

__device__ __forceinline__ void ld_chunk(const float* __restrict__ A,
                                         const float* __restrict__ W,
                                         int m0, int n0, int k0, int tid,
                                         float4* r) {
#pragma unroll
    for (int i = 0; i < 4; i++) {
        int f4  = tid + i * 256;
        int row = f4 >> 3;
        int c4  = (f4 & 7) << 2;
        r[i]     = *reinterpret_cast<const float4*>(A + (size_t)(m0 + row) * C_DIM + k0 + c4);
        r[4 + i] = *reinterpret_cast<const float4*>(W + (size_t)(n0 + row) * C_DIM + k0 + c4);
    }
}

__device__ __forceinline__ void st_chunk(char* buf, int tid, const float4* r) {
#pragma unroll
    for (int i = 0; i < 4; i++) {
        int f4  = tid + i * 256;
        int row = f4 >> 3;
        int c4  = (f4 & 7) << 2;
        int off = row * RB + c4 * 2;
        uint32_t h01, l01, h23, l23;
        split2(r[i].x, r[i].y, h01, l01);
        split2(r[i].z, r[i].w, h23, l23);
        *reinterpret_cast<uint2*>(buf + off)         = make_uint2(h01, h23);
        *reinterpret_cast<uint2*>(buf + REG_B + off) = make_uint2(l01, l23);
        split2(r[4 + i].x, r[4 + i].y, h01, l01);
        split2(r[4 + i].z, r[4 + i].w, h23, l23);
        *reinterpret_cast<uint2*>(buf + 2 * REG_B + off) = make_uint2(h01, h23);
        *reinterpret_cast<uint2*>(buf + 3 * REG_B + off) = make_uint2(l01, l23);
    }
}

__device__ __forceinline__ void compute_chunk_s(const char* sbuf, int wm, int wn,
                                                int lane, float acc[2][8][4]) {
    const int g = lane >> 2;
    const int t = lane & 3;
#pragma unroll
    for (int ks = 0; ks < 32; ks += 16) {
        uint32_t ah[2][4], al[2][4];
#pragma unroll
        for (int mt = 0; mt < 2; mt++) {
            const char* a0p = sbuf + (wm + mt * 16 + g) * RB + (ks + 2 * t) * 2;
            ah[mt][0] = lds32(a0p);
            ah[mt][1] = lds32(a0p + 8 * RB);
            ah[mt][2] = lds32(a0p + 16);
            ah[mt][3] = lds32(a0p + 8 * RB + 16);
            al[mt][0] = lds32(a0p + REG_B);
            al[mt][1] = lds32(a0p + REG_B + 8 * RB);
            al[mt][2] = lds32(a0p + REG_B + 16);
            al[mt][3] = lds32(a0p + REG_B + 8 * RB + 16);
        }
#pragma unroll
        for (int qh = 0; qh < 2; qh++) {
            uint32_t bh[4][2], bl[4][2];
#pragma unroll
            for (int q4 = 0; q4 < 4; q4++) {
                const char* b0p = sbuf + 2 * REG_B
                    + (wn + (qh * 4 + q4) * 8 + g) * RB + (ks + 2 * t) * 2;
                bh[q4][0] = lds32(b0p);
                bh[q4][1] = lds32(b0p + 16);
                bl[q4][0] = lds32(b0p + REG_B);
                bl[q4][1] = lds32(b0p + REG_B + 16);
            }
#pragma unroll
            for (int q4 = 0; q4 < 4; q4++)
#pragma unroll
                for (int mt = 0; mt < 2; mt++)
                    mma16816(acc[mt][qh * 4 + q4], ah[mt], bh[q4]);
#pragma unroll
            for (int q4 = 0; q4 < 4; q4++)
#pragma unroll
                for (int mt = 0; mt < 2; mt++)
                    mma16816(acc[mt][qh * 4 + q4], ah[mt], bl[q4]);
#pragma unroll
            for (int q4 = 0; q4 < 4; q4++)
#pragma unroll
                for (int mt = 0; mt < 2; mt++)
                    mma16816(acc[mt][qh * 4 + q4], al[mt], bh[q4]);
        }
    }
}

__device__ __forceinline__ void hgemm_body(char* smem,
                                           const float* __restrict__ A,
                                           const float* __restrict__ W,
                                           const float* __restrict__ bias,
                                           float* __restrict__ C, int Ntot) {
    const int tid  = threadIdx.x;
    const int wid  = tid >> 5;
    const int lane = tid & 31;
    const int m0 = blockIdx.y * 128;
    const int n0 = blockIdx.x * 128;
    const int wm = (wid >> 1) * 32;
    const int wn = (wid & 1) * 64;

    float acc[2][8][4];
#pragma unroll
    for (int mt = 0; mt < 2; mt++)
#pragma unroll
        for (int nt = 0; nt < 8; nt++)
#pragma unroll
            for (int j = 0; j < 4; j++) acc[mt][nt][j] = 0.f;

    float4 pref[8];
    ld_chunk(A, W, m0, n0, 0, tid, pref);
    st_chunk(smem, tid, pref);
    __syncthreads();

#pragma unroll 1
    for (int ch = 0; ch < 8; ch++) {
        if (ch < 7) ld_chunk(A, W, m0, n0, (ch + 1) * 32, tid, pref);
        compute_chunk_s(smem + (ch & 1) * BUF_B, wm, wn, lane, acc);
        if (ch < 7) st_chunk(smem + ((ch + 1) & 1) * BUF_B, tid, pref);
        __syncthreads();
    }

    const int g = lane >> 2;
    const int t = lane & 3;
#pragma unroll
    for (int mt = 0; mt < 2; mt++) {
#pragma unroll
        for (int q = 0; q < 8; q++) {
            int rr = m0 + wm + mt * 16 + g;
            int cc = n0 + wn + q * 8 + 2 * t;
            float b0 = bias[cc], b1 = bias[cc + 1];
            float2 v0 = make_float2(acc[mt][q][0] + b0, acc[mt][q][1] + b1);
            float2 v1 = make_float2(acc[mt][q][2] + b0, acc[mt][q][3] + b1);
            *reinterpret_cast<float2*>(C + (size_t)rr * Ntot + cc)       = v0;
            *reinterpret_cast<float2*>(C + (size_t)(rr + 8) * Ntot + cc) = v1;
        }
    }
}

__global__ void __launch_bounds__(256, 2)
qkv_gemm_kernel(const float* __restrict__ x, const float* __restrict__ w,
                const float* __restrict__ b) {
    extern __shared__ char smem[];
    hgemm_body(smem, x, w, b, g_qkv, QKV_N);
}

__global__ void __launch_bounds__(256, 2)
proj_gemm_kernel(const float* __restrict__ w, const float* __restrict__ b,
                 float* __restrict__ out) {
    extern __shared__ char smem[];
    hgemm_body(smem, g_att, w, b, out, C_DIM);
}

// ---------------------------------------------------------------
// Kernel 3: HMMA attention, 112-padding, 7 warps (224 threads).
// Each warp owns 16 rows x 112 cols (acc[14][4]); warp-local softmax;
// PV builds A fragments from registers. One __syncthreads total.
// smem = qk 4*8960 + vt 2*7680 = 51200 -> 2 CTAs/SM.
// ---------------------------------------------------------------
#define NP     112
#define REG_B2 (NP * RB)          // 8960
#define VRB2   240
#define VREG2  (HD * VRB2)        // 7680
#define OFF_VT2   (4 * REG_B2)           // 35840
#define ATTN_SMEM (OFF_VT2 + 2 * VREG2)  // 51200
#define ATHREADS  224

__global__ void __launch_bounds__(ATHREADS, 2)
attn_hmma_kernel(const float* __restrict__ mask) {
    extern __shared__ char smem[];
    const int tid  = threadIdx.x;
    const int wid  = tid >> 5;           // 0..6
    const int lane = tid & 31;
    const int g = lane >> 2;
    const int t = lane & 3;
    const int bh = blockIdx.x;
    const int b  = bh >> 3;
    const int h  = bh & 7;
    const float scale = 0.17677669529663687f;   // 1/sqrt(32)

    char*  qk = smem;                    // q hi/lo, k hi/lo (112 rows, RB=80)
    char*  vt = smem + OFF_VT2;
    const uint32_t sb = smem_u32(smem);

    // ---- phase 0: load q (scaled), k; split; build V^T ----
#pragma unroll
    for (int i = 0; i < 4; i++) {
        int s = tid + ATHREADS * i;     // 896 slots: 112 rows x 8 quads
        int row = s >> 3;
        int c4  = (s & 7) << 2;
        float4 qv = make_float4(0.f, 0.f, 0.f, 0.f);
        float4 kv = qv;
        if (row < N_TOK) {
            size_t base = ((size_t)(b * N_TOK + row)) * QKV_N + h * HD + c4;
            qv = *reinterpret_cast<const float4*>(g_qkv + base);
            kv = *reinterpret_cast<const float4*>(g_qkv + base + C_DIM);
            qv.x *= scale; qv.y *= scale; qv.z *= scale; qv.w *= scale;
        }
        int off = row * RB + c4 * 2;
        uint32_t h01, l01, h23, l23;
        split2(qv.x, qv.y, h01, l01);
        split2(qv.z, qv.w, h23, l23);
        *reinterpret_cast<uint2*>(qk + off)              = make_uint2(h01, h23);
        *reinterpret_cast<uint2*>(qk + REG_B2 + off)     = make_uint2(l01, l23);
        split2(kv.x, kv.y, h01, l01);
        split2(kv.z, kv.w, h23, l23);
        *reinterpret_cast<uint2*>(qk + 2 * REG_B2 + off) = make_uint2(h01, h23);
        *reinterpret_cast<uint2*>(qk + 3 * REG_B2 + off) = make_uint2(l01, l23);
    }
    // V^T: vt[d][token-pair] bf16 hi/lo; 56 token-pairs x 8 d-quads = 448 slots
#pragma unroll
    for (int i = 0; i < 2; i++) {
        int s  = tid + ATHREADS * i;
        int tp = s >> 3;                // 0..55
        int d4 = (s & 7) << 2;
        int t0 = 2 * tp, t1 = 2 * tp + 1;
        float4 v0 = make_float4(0.f, 0.f, 0.f, 0.f), v1 = v0;
        if (t0 < N_TOK)
            v0 = *reinterpret_cast<const float4*>(
                g_qkv + ((size_t)(b * N_TOK + t0)) * QKV_N + 2 * C_DIM + h * HD + d4);
        if (t1 < N_TOK)
            v1 = *reinterpret_cast<const float4*>(
                g_qkv + ((size_t)(b * N_TOK + t1)) * QKV_N + 2 * C_DIM + h * HD + d4);
        float e0[4] = { v0.x, v0.y, v0.z, v0.w };
        float e1[4] = { v1.x, v1.y, v1.z, v1.w };
#pragma unroll
        for (int d = 0; d < 4; d++) {
            uint32_t hi, lo;
            split2(e0[d], e1[d], hi, lo);
            *reinterpret_cast<uint32_t*>(vt + (d4 + d) * VRB2 + tp * 4)         = hi;
            *reinterpret_cast<uint32_t*>(vt + VREG2 + (d4 + d) * VRB2 + tp * 4) = lo;
        }
    }
    __syncthreads();   // THE only block-wide sync

    // ---- phase 1: S = q k^T. Warp wid owns rows [wm, wm+16). ----
    const int wm = wid * 16;
    const int arow  = lane & 15;
    const int acol2 = ((lane >> 4) << 3) * 2;
    const int brow  = (lane & 7) + ((lane >> 3) & 2) * 4;
    const int bcol2 = (((lane >> 3) & 1) << 3) * 2;

    float acc[14][4];
#pragma unroll
    for (int q = 0; q < 14; q++)
#pragma unroll
        for (int j = 0; j < 4; j++) acc[q][j] = 0.f;

#pragma unroll
    for (int ks = 0; ks < 32; ks += 16) {
        uint32_t ah[4], al[4];
        uint32_t aaddr = sb + (wm + arow) * RB + ks * 2 + acol2;
        ldsm4(ah, aaddr);
        ldsm4(al, aaddr + REG_B2);
#pragma unroll
        for (int qp = 0; qp < 7; qp++) {
            uint32_t baddr = sb + 2 * REG_B2 + (qp * 16 + brow) * RB + ks * 2 + bcol2;
            uint32_t bh[4], bl[4];
            ldsm4(bh, baddr);
            ldsm4(bl, baddr + REG_B2);
#pragma unroll
            for (int hf = 0; hf < 2; hf++)
                mma16816(acc[qp * 2 + hf], ah, bh + 2 * hf);
#pragma unroll
            for (int hf = 0; hf < 2; hf++)
                mma16816(acc[qp * 2 + hf], ah, bl + 2 * hf);
#pragma unroll
            for (int hf = 0; hf < 2; hf++)
                mma16816(acc[qp * 2 + hf], al, bh + 2 * hf);
        }
    }

    // ---- phase 2: add bias + mask; pad cells = -1e9 ----
    {
        const float* bp = g_bias + (size_t)h * (N_TOK * N_TOK);
        const float* mp = mask + (size_t)(b & (NW - 1)) * (N_TOK * N_TOK);
        const int rr0 = wm + g;
        const int rr1 = rr0 + 8;
#pragma unroll
        for (int q = 0; q < 14; q++) {
            int cc = q * 8 + 2 * t;
            if (cc < N_TOK && rr0 < N_TOK) {
                float2 bb = *reinterpret_cast<const float2*>(bp + rr0 * N_TOK + cc);
                float2 mm = *reinterpret_cast<const float2*>(mp + rr0 * N_TOK + cc);
                acc[q][0] += bb.x + mm.x;
                acc[q][1] += bb.y + mm.y;
            } else {
                acc[q][0] = -1e9f;
                acc[q][1] = -1e9f;
            }
            if (cc < N_TOK && rr1 < N_TOK) {
                float2 bb = *reinterpret_cast<const float2*>(bp + rr1 * N_TOK + cc);
                float2 mm = *reinterpret_cast<const float2*>(mp + rr1 * N_TOK + cc);
                acc[q][2] += bb.x + mm.x;
                acc[q][3] += bb.y + mm.y;
            } else {
                acc[q][2] = -1e9f;
                acc[q][3] = -1e9f;
            }
        }
    }

    // ---- phase 3: warp-local softmax (rows entirely in quad) ----
    float inv0, inv1;
    {
        float m0 = -1e30f, m1 = -1e30f;
#pragma unroll
        for (int q = 0; q < 14; q++) {
            m0 = fmaxf(m0, fmaxf(acc[q][0], acc[q][1]));
            m1 = fmaxf(m1, fmaxf(acc[q][2], acc[q][3]));
        }
#pragma unroll
        for (int off = 1; off <= 2; off <<= 1) {
            m0 = fmaxf(m0, __shfl_xor_sync(0xFFFFFFFFu, m0, off));
            m1 = fmaxf(m1, __shfl_xor_sync(0xFFFFFFFFu, m1, off));
        }
        float s0 = 0.f, s1 = 0.f;
#pragma unroll
        for (int q = 0; q < 14; q++) {
            float e0 = __expf(acc[q][0] - m0);
            float e1 = __expf(acc[q][1] - m0);
            float e2 = __expf(acc[q][2] - m1);
            float e3 = __expf(acc[q][3] - m1);
            acc[q][0] = e0; acc[q][1] = e1;
            acc[q][2] = e2; acc[q][3] = e3;
            s0 += e0 + e1;
            s1 += e2 + e3;
        }
#pragma unroll
        for (int off = 1; off <= 2; off <<= 1) {
            s0 += __shfl_xor_sync(0xFFFFFFFFu, s0, off);
            s1 += __shfl_xor_sync(0xFFFFFFFFu, s1, off);
        }
        inv0 = 1.f / s0;
        inv1 = 1.f / s1;
    }

    // ---- phase 4: O = P~ V via mma; A fragments built from registers ----
    float oacc[4][4];
#pragma unroll
    for (int nt = 0; nt < 4; nt++)
#pragma unroll
        for (int j = 0; j < 4; j++) oacc[nt][j] = 0.f;

#pragma unroll
    for (int kc = 0; kc < 7; kc++) {
        uint32_t ah[4], al[4];
        split2(acc[2 * kc][0],     acc[2 * kc][1],     ah[0], al[0]);
        split2(acc[2 * kc][2],     acc[2 * kc][3],     ah[1], al[1]);
        split2(acc[2 * kc + 1][0], acc[2 * kc + 1][1], ah[2], al[2]);
        split2(acc[2 * kc + 1][2], acc[2 * kc + 1][3], ah[3], al[3]);
#pragma unroll
        for (int np = 0; np < 2; np++) {
            uint32_t baddr = sb + OFF_VT2 + (np * 16 + brow) * VRB2 + kc * 32 + bcol2;
            uint32_t bh[4], bl[4];
            ldsm4(bh, baddr);
            ldsm4(bl, baddr + VREG2);
#pragma unroll
            for (int hf = 0; hf < 2; hf++) {
                int nt = np * 2 + hf;
                mma16816(oacc[nt], ah, bh + 2 * hf);
                mma16816(oacc[nt], ah, bl + 2 * hf);
                mma16816(oacc[nt], al, bh + 2 * hf);
            }
        }
    }

    // ---- phase 5: normalize + write O (fp32 g_att), rows < 98 ----
    {
        const int rr0 = wm + g;
        const int rr1 = rr0 + 8;
#pragma unroll
        for (int nt = 0; nt < 4; nt++) {
            int cc = h * HD + nt * 8 + 2 * t;
            if (rr0 < N_TOK)
                *reinterpret_cast<float2*>(g_att + (size_t)(b * N_TOK + rr0) * C_DIM + cc)
                    = make_float2(oacc[nt][0] * inv0, oacc[nt][1] * inv0);
            if (rr1 < N_TOK)
                *reinterpret_cast<float2*>(g_att + (size_t)(b * N_TOK + rr1) * C_DIM + cc)
                    = make_float2(oacc[nt][2] * inv1, oacc[nt][3] * inv1);
        }
    }
}

// ---------------------------------------------------------------
// Launch
// ---------------------------------------------------------------
extern "C" void kernel_launch(void* const* d_in, const int* in_sizes, int n_in,
                              void* d_out, int out_size) {
    const float* x          = (const float*)d_in[0];
    const float* mask       = (const float*)d_in[1];
    const float* qkv_w      = (const float*)d_in[2];
    const float* qkv_b      = (const float*)d_in[3];
    const float* proj_w     = (const float*)d_in[4];
    const float* proj_b     = (const float*)d_in[5];
    const float* bias_table = (const float*)d_in[6];
    const int*   rel_index  = (const int*)d_in[7];
    float* out = (float*)d_out;

    cudaFuncSetAttribute(attn_hmma_kernel,
                         cudaFuncAttributeMaxDynamicSharedMemorySize, ATTN_SMEM);
    const int gemm_smem = 2 * BUF_B;   // 81920
    cudaFuncSetAttribute(qkv_gemm_kernel,
                         cudaFuncAttributeMaxDynamicSharedMemorySize, gemm_smem);
    cudaFuncSetAttribute(proj_gemm_kernel,
                         cudaFuncAttributeMaxDynamicSharedMemorySize, gemm_smem);

    // 1) bias gather
    {
        int total = H_NUM * N_TOK * N_TOK;
        gather_bias_kernel<<<(total + 255) / 256, 256>>>(bias_table, rel_index);
    }
    // 2) QKV projection (HMMA bf16x3): [200704,256] x [768,256]^T -> g_qkv
    {
        dim3 grid(QKV_N / 128, M_ROWS / 128);
        qkv_gemm_kernel<<<grid, 256, gemm_smem>>>(x, qkv_w, qkv_b);
    }
    // 3) HMMA attention per (b,h), 112-pad, register P + warp softmax
    {
        attn_hmma_kernel<<<B_TOT * H_NUM, ATHREADS, ATTN_SMEM>>>(mask);
    }
    // 4) output projection (HMMA bf16x3): [200704,256] x [256,256]^T -> d_out
    {
        dim3 grid(C_DIM / 128, M_ROWS / 128);
        proj_gemm_kernel<<<grid, 256, gemm_smem>>>(proj_w, proj_b, out);
    }
}

// round 16
// speedup vs baseline: 1.2720x; 1.0214x over previous
#include <cuda_runtime.h>
#include <cuda_bf16.h>
#include <cstdint>

// Problem constants
#define B_TOT   2048
#define N_TOK   98
#define C_DIM   256
#define H_NUM   8
#define HD      32
#define NW      512
#define M_ROWS  (B_TOT * N_TOK)          // 200704
#define QKV_N   (3 * C_DIM)              // 768

// -------- scratch (static device globals; device-code refs ONLY) --------
// Packed format: one uint32 per element = bf16_hi | (bf16_lo << 16).
__device__ uint32_t g_qkv_p[(size_t)M_ROWS * QKV_N];   // 616 MB
__device__ uint32_t g_att_p[(size_t)M_ROWS * C_DIM];   // 205 MB
__device__ float g_bias[H_NUM * N_TOK * N_TOK];

// ================= helpers =================
__device__ __forceinline__ uint32_t smem_u32(const void* p) {
    uint32_t a;
    asm("{ .reg .u64 t; cvta.to.shared.u64 t, %1; cvt.u32.u64 %0, t; }"
        : "=r"(a) : "l"(p));
    return a;
}

__device__ __forceinline__ void mma16816(float* c, const uint32_t* a, const uint32_t* b) {
    asm volatile(
        "mma.sync.aligned.m16n8k16.row.col.f32.bf16.bf16.f32 "
        "{%0,%1,%2,%3}, {%4,%5,%6,%7}, {%8,%9}, {%0,%1,%2,%3};"
        : "+f"(c[0]), "+f"(c[1]), "+f"(c[2]), "+f"(c[3])
        : "r"(a[0]), "r"(a[1]), "r"(a[2]), "r"(a[3]), "r"(b[0]), "r"(b[1]));
}

__device__ __forceinline__ void ldsm4(uint32_t* r, uint32_t addr) {
    asm volatile("ldmatrix.sync.aligned.m8n8.x4.shared.b16 {%0,%1,%2,%3}, [%4];"
                 : "=r"(r[0]), "=r"(r[1]), "=r"(r[2]), "=r"(r[3]) : "r"(addr));
}

__device__ __forceinline__ void split2(float x, float y, uint32_t& hi, uint32_t& lo) {
    __nv_bfloat16 hx = __float2bfloat16(x);
    __nv_bfloat16 hy = __float2bfloat16(y);
    __nv_bfloat16 lx = __float2bfloat16(x - __bfloat162float(hx));
    __nv_bfloat16 ly = __float2bfloat16(y - __bfloat162float(hy));
    hi = (uint32_t)__bfloat16_as_ushort(hx) | ((uint32_t)__bfloat16_as_ushort(hy) << 16);
    lo = (uint32_t)__bfloat16_as_ushort(lx) | ((uint32_t)__bfloat16_as_ushort(ly) << 16);
}

__device__ __forceinline__ uint32_t prmt(uint32_t a, uint32_t b, uint32_t sel) {
    uint32_t d;
    asm("prmt.b32 %0, %1, %2, %3;" : "=r"(d) : "r"(a), "r"(b), "r"(sel));
    return d;
}
// packed pair (p0,p1) -> hi-pair / lo-pair
#define SEL_HI 0x5410u
#define SEL_LO 0x7632u

__device__ __forceinline__ uint32_t lds32(const char* p) {
    return *reinterpret_cast<const uint32_t*>(p);
}

// ---------------------------------------------------------------
// Kernel 1: gather relative-position bias  -> g_bias[h][n][m]
// ---------------------------------------------------------------
__global__ void gather_bias_kernel(const float* __restrict__ table,
                                   const int* __restrict__ rel) {
    int idx = blockIdx.x * blockDim.x + threadIdx.x;
    const int total = H_NUM * N_TOK * N_TOK;
    if (idx < total) {
        int h  = idx / (N_TOK * N_TOK);
        int nm = idx % (N_TOK * N_TOK);
        g_bias[idx] = table[rel[nm] * H_NUM + h];
    }
}

// ---------------------------------------------------------------
// HMMA bf16x3 split GEMM (R15 skeleton). APACK: A is packed hi|lo;
// OPACK: output stored packed (with q prescale for cols < 256).
// ---------------------------------------------------------------
#define RB    80          // row bytes (40 halves)
#define REG_B 10240       // region bytes
#define BUF_B 40960       // buffer bytes

__device__ __forceinline__ void compute_chunk_s(const char* sbuf, int wm, int wn,
                                                int lane, float acc[2][8][4]) {
    const int g = lane >> 2;
    const int t = lane & 3;
#pragma unroll
    for (int ks = 0; ks < 32; ks += 16) {
        uint32_t ah[2][4], al[2][4];
#pragma unroll
        for (int mt = 0; mt < 2; mt++) {
            const char* a0p = sbuf + (wm + mt * 16 + g) * RB + (ks + 2 * t) * 2;
            ah[mt][0] = lds32(a0p);
            ah[mt][1] = lds32(a0p + 8 * RB);
            ah[mt][2] = lds32(a0p + 16);
            ah[mt][3] = lds32(a0p + 8 * RB + 16);
            al[mt][0] = lds32(a0p + REG_B);
            al[mt][1] = lds32(a0p + REG_B + 8 * RB);
            al[mt][2] = lds32(a0p + REG_B + 16);
            al[mt][3] = lds32(a0p + REG_B + 8 * RB + 16);
        }
#pragma unroll
        for (int qh = 0; qh < 2; qh++) {
            uint32_t bh[4][2], bl[4][2];
#pragma unroll
            for (int q4 = 0; q4 < 4; q4++) {
                const char* b0p = sbuf + 2 * REG_B
                    + (wn + (qh * 4 + q4) * 8 + g) * RB + (ks + 2 * t) * 2;
                bh[q4][0] = lds32(b0p);
                bh[q4][1] = lds32(b0p + 16);
                bl[q4][0] = lds32(b0p + REG_B);
                bl[q4][1] = lds32(b0p + REG_B + 16);
            }
#pragma unroll
            for (int q4 = 0; q4 < 4; q4++)
#pragma unroll
                for (int mt = 0; mt < 2; mt++)
                    mma16816(acc[mt][qh * 4 + q4], ah[mt], bh[q4]);
#pragma unroll
            for (int q4 = 0; q4 < 4; q4++)
#pragma unroll
                for (int mt = 0; mt < 2; mt++)
                    mma16816(acc[mt][qh * 4 + q4], ah[mt], bl[q4]);
#pragma unroll
            for (int q4 = 0; q4 < 4; q4++)
#pragma unroll
                for (int mt = 0; mt < 2; mt++)
                    mma16816(acc[mt][qh * 4 + q4], al[mt], bh[q4]);
        }
    }
}

template <bool APACK, bool OPACK>
__device__ __forceinline__ void hgemm_body(char* smem,
                                           const uint32_t* __restrict__ Av,  // elems (fp32 bits or packed)
                                           const float* __restrict__ W,
                                           const float* __restrict__ bias,
                                           void* __restrict__ Cv,
                                           int Ntot) {
    const int tid  = threadIdx.x;
    const int wid  = tid >> 5;
    const int lane = tid & 31;
    const int m0 = blockIdx.y * 128;
    const int n0 = blockIdx.x * 128;
    const int wm = (wid >> 1) * 32;
    const int wn = (wid & 1) * 64;

    float acc[2][8][4];
#pragma unroll
    for (int mt = 0; mt < 2; mt++)
#pragma unroll
        for (int nt = 0; nt < 8; nt++)
#pragma unroll
            for (int j = 0; j < 4; j++) acc[mt][nt][j] = 0.f;

    uint4  ra[4];
    float4 rw[4];

    auto ld = [&](int k0) {
#pragma unroll
        for (int i = 0; i < 4; i++) {
            int f4  = tid + i * 256;
            int row = f4 >> 3;
            int c4  = (f4 & 7) << 2;
            ra[i] = *reinterpret_cast<const uint4*>(Av + (size_t)(m0 + row) * C_DIM + k0 + c4);
            rw[i] = *reinterpret_cast<const float4*>(W + (size_t)(n0 + row) * C_DIM + k0 + c4);
        }
    };
    auto st = [&](char* buf) {
#pragma unroll
        for (int i = 0; i < 4; i++) {
            int f4  = tid + i * 256;
            int row = f4 >> 3;
            int c4  = (f4 & 7) << 2;
            int off = row * RB + c4 * 2;
            uint32_t h01, l01, h23, l23;
            if (APACK) {
                h01 = prmt(ra[i].x, ra[i].y, SEL_HI);
                l01 = prmt(ra[i].x, ra[i].y, SEL_LO);
                h23 = prmt(ra[i].z, ra[i].w, SEL_HI);
                l23 = prmt(ra[i].z, ra[i].w, SEL_LO);
            } else {
                float4 f = *reinterpret_cast<const float4*>(&ra[i]);
                split2(f.x, f.y, h01, l01);
                split2(f.z, f.w, h23, l23);
            }
            *reinterpret_cast<uint2*>(buf + off)         = make_uint2(h01, h23);
            *reinterpret_cast<uint2*>(buf + REG_B + off) = make_uint2(l01, l23);
            split2(rw[i].x, rw[i].y, h01, l01);
            split2(rw[i].z, rw[i].w, h23, l23);
            *reinterpret_cast<uint2*>(buf + 2 * REG_B + off) = make_uint2(h01, h23);
            *reinterpret_cast<uint2*>(buf + 3 * REG_B + off) = make_uint2(l01, l23);
        }
    };

    ld(0);
    st(smem);
    __syncthreads();

#pragma unroll 1
    for (int ch = 0; ch < 8; ch++) {
        if (ch < 7) ld((ch + 1) * 32);
        compute_chunk_s(smem + (ch & 1) * BUF_B, wm, wn, lane, acc);
        if (ch < 7) st(smem + ((ch + 1) & 1) * BUF_B);
        __syncthreads();
    }

    const int g = lane >> 2;
    const int t = lane & 3;
    const float f = (OPACK && n0 < 256) ? 0.17677669529663687f : 1.f;
#pragma unroll
    for (int mt = 0; mt < 2; mt++) {
#pragma unroll
        for (int q = 0; q < 8; q++) {
            int rr = m0 + wm + mt * 16 + g;
            int cc = n0 + wn + q * 8 + 2 * t;
            float b0 = bias[cc], b1 = bias[cc + 1];
            float v00 = acc[mt][q][0] + b0, v01 = acc[mt][q][1] + b1;
            float v10 = acc[mt][q][2] + b0, v11 = acc[mt][q][3] + b1;
            if (OPACK) {
                uint32_t hi, lo;
                split2(v00 * f, v01 * f, hi, lo);
                *reinterpret_cast<uint2*>((uint32_t*)Cv + (size_t)rr * Ntot + cc)
                    = make_uint2(prmt(hi, lo, SEL_HI), prmt(hi, lo, SEL_LO));
                split2(v10 * f, v11 * f, hi, lo);
                *reinterpret_cast<uint2*>((uint32_t*)Cv + (size_t)(rr + 8) * Ntot + cc)
                    = make_uint2(prmt(hi, lo, SEL_HI), prmt(hi, lo, SEL_LO));
            } else {
                *reinterpret_cast<float2*>((float*)Cv + (size_t)rr * Ntot + cc)
                    = make_float2(v00, v01);
                *reinterpret_cast<float2*>((float*)Cv + (size_t)(rr + 8) * Ntot + cc)
                    = make_float2(v10, v11);
            }
        }
    }
}

__global__ void __launch_bounds__(256, 2)
qkv_gemm_kernel(const float* __restrict__ x, const float* __restrict__ w,
                const float* __restrict__ b) {
    extern __shared__ char smem[];
    hgemm_body<false, true>(smem, reinterpret_cast<const uint32_t*>(x), w, b,
                            g_qkv_p, QKV_N);
}

__global__ void __launch_bounds__(256, 2)
proj_gemm_kernel(const float* __restrict__ w, const float* __restrict__ b,
                 float* __restrict__ out) {
    extern __shared__ char smem[];
    hgemm_body<true, false>(smem, g_att_p, w, b, out, C_DIM);
}

// ---------------------------------------------------------------
// Kernel 3: HMMA attention, 112-pad, 7 warps, packed inputs.
// Phase 0 is pure LDG -> PRMT -> STS (q prescaled upstream).
// smem = qk 4*8960 + vt 2*7680 = 51200 -> 2 CTAs/SM.
// ---------------------------------------------------------------
#define NP     112
#define REG_B2 (NP * RB)          // 8960
#define VRB2   240
#define VREG2  (HD * VRB2)        // 7680
#define OFF_VT2   (4 * REG_B2)           // 35840
#define ATTN_SMEM (OFF_VT2 + 2 * VREG2)  // 51200
#define ATHREADS  224

__global__ void __launch_bounds__(ATHREADS, 2)
attn_hmma_kernel(const float* __restrict__ mask) {
    extern __shared__ char smem[];
    const int tid  = threadIdx.x;
    const int wid  = tid >> 5;           // 0..6
    const int lane = tid & 31;
    const int g = lane >> 2;
    const int t = lane & 3;
    const int bh = blockIdx.x;
    const int b  = bh >> 3;
    const int h  = bh & 7;

    char*  qk = smem;
    char*  vt = smem + OFF_VT2;
    const uint32_t sb = smem_u32(smem);

    // ---- phase 0: copy packed q,k (PRMT unpack); build V^T ----
#pragma unroll
    for (int i = 0; i < 4; i++) {
        int s = tid + ATHREADS * i;     // 896 slots: 112 rows x 8 quads
        int row = s >> 3;
        int c4  = (s & 7) << 2;
        uint4 qp = make_uint4(0u, 0u, 0u, 0u), kp = qp;
        if (row < N_TOK) {
            size_t base = ((size_t)(b * N_TOK + row)) * QKV_N + h * HD + c4;
            qp = *reinterpret_cast<const uint4*>(g_qkv_p + base);
            kp = *reinterpret_cast<const uint4*>(g_qkv_p + base + C_DIM);
        }
        int off = row * RB + c4 * 2;
        *reinterpret_cast<uint2*>(qk + off)
            = make_uint2(prmt(qp.x, qp.y, SEL_HI), prmt(qp.z, qp.w, SEL_HI));
        *reinterpret_cast<uint2*>(qk + REG_B2 + off)
            = make_uint2(prmt(qp.x, qp.y, SEL_LO), prmt(qp.z, qp.w, SEL_LO));
        *reinterpret_cast<uint2*>(qk + 2 * REG_B2 + off)
            = make_uint2(prmt(kp.x, kp.y, SEL_HI), prmt(kp.z, kp.w, SEL_HI));
        *reinterpret_cast<uint2*>(qk + 3 * REG_B2 + off)
            = make_uint2(prmt(kp.x, kp.y, SEL_LO), prmt(kp.z, kp.w, SEL_LO));
    }
    // V^T: vt[d][token-pair]; 56 token-pairs x 8 d-quads = 448 slots
#pragma unroll
    for (int i = 0; i < 2; i++) {
        int s  = tid + ATHREADS * i;
        int tp = s >> 3;                // 0..55
        int d4 = (s & 7) << 2;
        int t0 = 2 * tp, t1 = 2 * tp + 1;
        uint4 p0 = make_uint4(0u, 0u, 0u, 0u), p1 = p0;
        if (t0 < N_TOK)
            p0 = *reinterpret_cast<const uint4*>(
                g_qkv_p + ((size_t)(b * N_TOK + t0)) * QKV_N + 2 * C_DIM + h * HD + d4);
        if (t1 < N_TOK)
            p1 = *reinterpret_cast<const uint4*>(
                g_qkv_p + ((size_t)(b * N_TOK + t1)) * QKV_N + 2 * C_DIM + h * HD + d4);
        uint32_t e0[4] = { p0.x, p0.y, p0.z, p0.w };
        uint32_t e1[4] = { p1.x, p1.y, p1.z, p1.w };
#pragma unroll
        for (int d = 0; d < 4; d++) {
            // word = tok0 | tok1<<16 for hi and lo planes
            *reinterpret_cast<uint32_t*>(vt + (d4 + d) * VRB2 + tp * 4)
                = prmt(e0[d], e1[d], SEL_HI);
            *reinterpret_cast<uint32_t*>(vt + VREG2 + (d4 + d) * VRB2 + tp * 4)
                = prmt(e0[d], e1[d], SEL_LO);
        }
    }
    __syncthreads();   // THE only block-wide sync

    // ---- phase 1: S = q k^T. Warp wid owns rows [wm, wm+16). ----
    const int wm = wid * 16;
    const int arow  = lane & 15;
    const int acol2 = ((lane >> 4) << 3) * 2;
    const int brow  = (lane & 7) + ((lane >> 3) & 2) * 4;
    const int bcol2 = (((lane >> 3) & 1) << 3) * 2;

    float acc[14][4];
#pragma unroll
    for (int q = 0; q < 14; q++)
#pragma unroll
        for (int j = 0; j < 4; j++) acc[q][j] = 0.f;

#pragma unroll
    for (int ks = 0; ks < 32; ks += 16) {
        uint32_t ah[4], al[4];
        uint32_t aaddr = sb + (wm + arow) * RB + ks * 2 + acol2;
        ldsm4(ah, aaddr);
        ldsm4(al, aaddr + REG_B2);
#pragma unroll
        for (int qp = 0; qp < 7; qp++) {
            uint32_t baddr = sb + 2 * REG_B2 + (qp * 16 + brow) * RB + ks * 2 + bcol2;
            uint32_t bh[4], bl[4];
            ldsm4(bh, baddr);
            ldsm4(bl, baddr + REG_B2);
#pragma unroll
            for (int hf = 0; hf < 2; hf++)
                mma16816(acc[qp * 2 + hf], ah, bh + 2 * hf);
#pragma unroll
            for (int hf = 0; hf < 2; hf++)
                mma16816(acc[qp * 2 + hf], ah, bl + 2 * hf);
#pragma unroll
            for (int hf = 0; hf < 2; hf++)
                mma16816(acc[qp * 2 + hf], al, bh + 2 * hf);
        }
    }

    // ---- phase 2: add bias + mask; pad cells = -1e9 ----
    {
        const float* bp = g_bias + (size_t)h * (N_TOK * N_TOK);
        const float* mp = mask + (size_t)(b & (NW - 1)) * (N_TOK * N_TOK);
        const int rr0 = wm + g;
        const int rr1 = rr0 + 8;
#pragma unroll
        for (int q = 0; q < 14; q++) {
            int cc = q * 8 + 2 * t;
            if (cc < N_TOK && rr0 < N_TOK) {
                float2 bb = *reinterpret_cast<const float2*>(bp + rr0 * N_TOK + cc);
                float2 mm = *reinterpret_cast<const float2*>(mp + rr0 * N_TOK + cc);
                acc[q][0] += bb.x + mm.x;
                acc[q][1] += bb.y + mm.y;
            } else {
                acc[q][0] = -1e9f;
                acc[q][1] = -1e9f;
            }
            if (cc < N_TOK && rr1 < N_TOK) {
                float2 bb = *reinterpret_cast<const float2*>(bp + rr1 * N_TOK + cc);
                float2 mm = *reinterpret_cast<const float2*>(mp + rr1 * N_TOK + cc);
                acc[q][2] += bb.x + mm.x;
                acc[q][3] += bb.y + mm.y;
            } else {
                acc[q][2] = -1e9f;
                acc[q][3] = -1e9f;
            }
        }
    }

    // ---- phase 3: warp-local softmax (rows entirely in quad) ----
    float inv0, inv1;
    {
        float m0 = -1e30f, m1 = -1e30f;
#pragma unroll
        for (int q = 0; q < 14; q++) {
            m0 = fmaxf(m0, fmaxf(acc[q][0], acc[q][1]));
            m1 = fmaxf(m1, fmaxf(acc[q][2], acc[q][3]));
        }
#pragma unroll
        for (int off = 1; off <= 2; off <<= 1) {
            m0 = fmaxf(m0, __shfl_xor_sync(0xFFFFFFFFu, m0, off));
            m1 = fmaxf(m1, __shfl_xor_sync(0xFFFFFFFFu, m1, off));
        }
        float s0 = 0.f, s1 = 0.f;
#pragma unroll
        for (int q = 0; q < 14; q++) {
            float e0 = __expf(acc[q][0] - m0);
            float e1 = __expf(acc[q][1] - m0);
            float e2 = __expf(acc[q][2] - m1);
            float e3 = __expf(acc[q][3] - m1);
            acc[q][0] = e0; acc[q][1] = e1;
            acc[q][2] = e2; acc[q][3] = e3;
            s0 += e0 + e1;
            s1 += e2 + e3;
        }
#pragma unroll
        for (int off = 1; off <= 2; off <<= 1) {
            s0 += __shfl_xor_sync(0xFFFFFFFFu, s0, off);
            s1 += __shfl_xor_sync(0xFFFFFFFFu, s1, off);
        }
        inv0 = 1.f / s0;
        inv1 = 1.f / s1;
    }

    // ---- phase 4: O = P~ V via mma; A fragments built from registers ----
    float oacc[4][4];
#pragma unroll
    for (int nt = 0; nt < 4; nt++)
#pragma unroll
        for (int j = 0; j < 4; j++) oacc[nt][j] = 0.f;

#pragma unroll
    for (int kc = 0; kc < 7; kc++) {
        uint32_t ah[4], al[4];
        split2(acc[2 * kc][0],     acc[2 * kc][1],     ah[0], al[0]);
        split2(acc[2 * kc][2],     acc[2 * kc][3],     ah[1], al[1]);
        split2(acc[2 * kc + 1][0], acc[2 * kc + 1][1], ah[2], al[2]);
        split2(acc[2 * kc + 1][2], acc[2 * kc + 1][3], ah[3], al[3]);
#pragma unroll
        for (int np = 0; np < 2; np++) {
            uint32_t baddr = sb + OFF_VT2 + (np * 16 + brow) * VRB2 + kc * 32 + bcol2;
            uint32_t bh[4], bl[4];
            ldsm4(bh, baddr);
            ldsm4(bl, baddr + VREG2);
#pragma unroll
            for (int hf = 0; hf < 2; hf++) {
                int nt = np * 2 + hf;
                mma16816(oacc[nt], ah, bh + 2 * hf);
                mma16816(oacc[nt], ah, bl + 2 * hf);
                mma16816(oacc[nt], al, bh + 2 * hf);
            }
        }
    }

    // ---- phase 5: normalize + write O packed, rows < 98 ----
    {
        const int rr0 = wm + g;
        const int rr1 = rr0 + 8;
#pragma unroll
        for (int nt = 0; nt < 4; nt++) {
            int cc = h * HD + nt * 8 + 2 * t;
            uint32_t hi, lo;
            if (rr0 < N_TOK) {
                split2(oacc[nt][0] * inv0, oacc[nt][1] * inv0, hi, lo);
                *reinterpret_cast<uint2*>(g_att_p + (size_t)(b * N_TOK + rr0) * C_DIM + cc)
                    = make_uint2(prmt(hi, lo, SEL_HI), prmt(hi, lo, SEL_LO));
            }
            if (rr1 < N_TOK) {
                split2(oacc[nt][2] * inv1, oacc[nt][3] * inv1, hi, lo);
                *reinterpret_cast<uint2*>(g_att_p + (size_t)(b * N_TOK + rr1) * C_DIM + cc)
                    = make_uint2(prmt(hi, lo, SEL_HI), prmt(hi, lo, SEL_LO));
            }
        }
    }
}

// ---------------------------------------------------------------
// Launch
// ---------------------------------------------------------------
extern "C" void kernel_launch(void* const* d_in, const int* in_sizes, int n_in,
                              void* d_out, int out_size) {
    const float* x          = (const float*)d_in[0];
    const float* mask       = (const float*)d_in[1];
    const float* qkv_w      = (const float*)d_in[2];
    const float* qkv_b      = (const float*)d_in[3];
    const float* proj_w     = (const float*)d_in[4];
    const float* proj_b     = (const float*)d_in[5];
    const float* bias_table = (const float*)d_in[6];
    const int*   rel_index  = (const int*)d_in[7];
    float* out = (float*)d_out;

    cudaFuncSetAttribute(attn_hmma_kernel,
                         cudaFuncAttributeMaxDynamicSharedMemorySize, ATTN_SMEM);
    const int gemm_smem = 2 * BUF_B;   // 81920
    cudaFuncSetAttribute(qkv_gemm_kernel,
                         cudaFuncAttributeMaxDynamicSharedMemorySize, gemm_smem);
    cudaFuncSetAttribute(proj_gemm_kernel,
                         cudaFuncAttributeMaxDynamicSharedMemorySize, gemm_smem);

    // 1) bias gather
    {
        int total = H_NUM * N_TOK * N_TOK;
        gather_bias_kernel<<<(total + 255) / 256, 256>>>(bias_table, rel_index);
    }
    // 2) QKV projection (HMMA bf16x3) -> packed g_qkv_p (q prescaled)
    {
        dim3 grid(QKV_N / 128, M_ROWS / 128);
        qkv_gemm_kernel<<<grid, 256, gemm_smem>>>(x, qkv_w, qkv_b);
    }
    // 3) HMMA attention per (b,h), 112-pad, register P + warp softmax
    {
        attn_hmma_kernel<<<B_TOT * H_NUM, ATHREADS, ATTN_SMEM>>>(mask);
    }
    // 4) output projection (HMMA bf16x3, packed A) -> fp32 out
    {
        dim3 grid(C_DIM / 128, M_ROWS / 128);
        proj_gemm_kernel<<<grid, 256, gemm_smem>>>(proj_w, proj_b, out);
    }
}